// round 13
// baseline (speedup 1.0000x reference)
#include <cuda_runtime.h>
#include <cuda_bf16.h>
#include <stdint.h>
#include <math.h>

// ---------------- Problem constants ----------------
#define BATCH 512
#define C1 256
#define ROUTES 1152
#define NCAPS 10
#define CAPDIM 16
#define M2 (BATCH*36)     // 18432
#define K2 20736          // 256*81
#define N2 256
#define FLAT 9216

// ---------------- Device scratch ----------------
// g_big holds aimH+aimL (im2col planes, live until conv2), then uhat (after conv2).
// aimH+aimL bytes = 2 * M2*K2*2 = 1,528,823,808 ; uhat = 377,487,360.
#define BIG_BYTES ((size_t)M2 * K2 * 4)
#define PLANE_ELEMS ((size_t)M2 * K2)
__device__ __align__(128) unsigned char g_big[BIG_BYTES];
__device__ __align__(16) uint32_t g_x1p[BATCH*C1*20*20];          // packed bf16 hi|lo (210MB)
__device__ __align__(16) __nv_bfloat16 g_bpH[(size_t)N2*K2];      // B hi plane (10.6MB)
__device__ __align__(16) __nv_bfloat16 g_bpL[(size_t)N2*K2];      // B lo plane
__device__ __align__(16) int      g_kofft[K2];
__device__ __align__(16) float g_c2[BATCH*FLAT];
__device__ __align__(16) float g_u[BATCH*FLAT];
__device__ __align__(16) float g_bij[ROUTES*NCAPS];
__device__ __align__(16) float g_cij[ROUTES*NCAPS];
__device__ __align__(16) float g_v[BATCH*NCAPS*CAPDIM];
__device__ int   g_best[BATCH];
__device__ __align__(16) float g_h1[BATCH*512];
__device__ __align__(16) float g_h2[BATCH*1024];

// ---------------- helpers ----------------
__device__ __forceinline__ uint32_t pack_split(float x) {
    __nv_bfloat16 h = __float2bfloat16(x);
    __nv_bfloat16 l = __float2bfloat16(x - __bfloat162float(h));
    return (uint32_t)__bfloat16_as_ushort(h) | ((uint32_t)__bfloat16_as_ushort(l) << 16);
}

__global__ void bsplit_kernel(const float* __restrict__ w,
                              __nv_bfloat16* __restrict__ bh, __nv_bfloat16* __restrict__ bl) {
    int i = blockIdx.x * 1024 + threadIdx.x;
    if (i >= N2 * K2) return;
    float v = w[i];
    __nv_bfloat16 h = __float2bfloat16(v);
    bh[i] = h;
    bl[i] = __float2bfloat16(v - __bfloat162float(h));
}

__global__ void kofft_kernel(int* __restrict__ tab) {
    int k = blockIdx.x * 256 + threadIdx.x;
    if (k >= K2) return;
    int ci = k / 81, rem = k - ci * 81;
    int ky = rem / 9, kx = rem - ky * 9;
    tab[k] = ci * 400 + ky * 20 + kx;
}

// ---------------- Conv1 -> packed split ----------------
__global__ void conv1_kernel(const float* __restrict__ img, const float* __restrict__ w,
                             const float* __restrict__ bias, uint32_t* __restrict__ x1p) {
    __shared__ float ism[784];
    __shared__ float wsm[32 * 81];
    int b = blockIdx.x, g = blockIdx.y;
    for (int i = threadIdx.x; i < 784; i += 256) ism[i] = img[b * 784 + i];
    for (int i = threadIdx.x; i < 2592; i += 256) wsm[i] = w[g * 2592 + i];
    __syncthreads();
    for (int idx = threadIdx.x; idx < 32 * 400; idx += 256) {
        int cl = idx / 400, pix = idx - cl * 400;
        int y = pix / 20, x = pix - y * 20;
        const float* wp = &wsm[cl * 81];
        float acc = bias[g * 32 + cl];
        #pragma unroll
        for (int ky = 0; ky < 9; ky++) {
            const float* irow = &ism[(y + ky) * 28 + x];
            #pragma unroll
            for (int kx = 0; kx < 9; kx++)
                acc += irow[kx] * wp[ky * 9 + kx];
        }
        x1p[(size_t)b * 102400 + (size_t)(g * 32 + cl) * 400 + pix] = pack_split(fmaxf(acc, 0.f));
    }
}

// ---------------- im2col: packed x1 -> separate H/L planes ----------------
__global__ void im2col_kernel(const uint32_t* __restrict__ x1p, const int* __restrict__ kofft,
                              __nv_bfloat16* __restrict__ aimH, __nv_bfloat16* __restrict__ aimL) {
    int m = blockIdx.x;
    int b = m / 36, s = m - b * 36;
    int oy = s / 6, ox = s - oy * 6;
    const uint32_t* base = x1p + (size_t)b * 102400 + oy * 40 + ox * 2;
    size_t off = (size_t)m * K2;
    for (int k = threadIdx.x; k < K2; k += 256) {
        uint32_t p = base[kofft[k]];
        aimH[off + k] = __ushort_as_bfloat16((unsigned short)(p & 0xFFFF));
        aimL[off + k] = __ushort_as_bfloat16((unsigned short)(p >> 16));
    }
}

// ---------------- Conv2: cp.async 3-stage pipeline + split-bf16 MMA ----------------
#define BK 16
#define LDS_PAD 24
#define STG_BYTES (128 * LDS_PAD * 2)   // 6144 per array per stage
#define OFF_AH 0
#define OFF_AL (3 * STG_BYTES)
#define OFF_BH (6 * STG_BYTES)
#define OFF_BL (9 * STG_BYTES)
#define SMEM_CONV2 (12 * STG_BYTES)     // 73728

#define CP_ASYNC16(sm, gp) \
    asm volatile("cp.async.cg.shared.global [%0], [%1], 16;" :: "r"(sm), "l"(gp) : "memory")
#define CP_COMMIT() asm volatile("cp.async.commit_group;" ::: "memory")
#define CP_WAIT1()  asm volatile("cp.async.wait_group 1;" ::: "memory")

__device__ __forceinline__ void mma_bf16(float& c0, float& c1, float& c2, float& c3,
                                         uint32_t a0, uint32_t a1, uint32_t a2, uint32_t a3,
                                         uint32_t b0, uint32_t b1) {
    asm volatile(
        "mma.sync.aligned.m16n8k16.row.col.f32.bf16.bf16.f32 "
        "{%0,%1,%2,%3}, {%4,%5,%6,%7}, {%8,%9}, {%0,%1,%2,%3};\n"
        : "+f"(c0), "+f"(c1), "+f"(c2), "+f"(c3)
        : "r"(a0), "r"(a1), "r"(a2), "r"(a3), "r"(b0), "r"(b1));
}

__global__ __launch_bounds__(512, 1)
void conv2_mma_kernel(const __nv_bfloat16* __restrict__ aimH, const __nv_bfloat16* __restrict__ aimL,
                      const __nv_bfloat16* __restrict__ bpH, const __nv_bfloat16* __restrict__ bpL,
                      const float* __restrict__ bias, float* __restrict__ out) {
    extern __shared__ char smem[];
    uint32_t sb;
    asm("{ .reg .u64 t; cvta.to.shared.u64 t, %1; cvt.u32.u64 %0, t; }" : "=r"(sb) : "l"(smem));

    const int t = threadIdx.x;
    const int m0 = blockIdx.y * 128;
    const int n0 = blockIdx.x * 128;

    // loader mapping: lr = t>>2 (row 0..127), h = (t>>1)&1 (k-chunk), ab = t&1 (A or B)
    const int lr = t >> 2;
    const int lh = (t >> 1) & 1;
    const int ab = t & 1;
    const __nv_bfloat16* gH = ab ? (bpH + (size_t)(n0 + lr) * K2 + lh * 8)
                                 : (aimH + (size_t)(m0 + lr) * K2 + lh * 8);
    const __nv_bfloat16* gL = ab ? (bpL + (size_t)(n0 + lr) * K2 + lh * 8)
                                 : (aimL + (size_t)(m0 + lr) * K2 + lh * 8);
    const uint32_t smH0 = sb + (ab ? OFF_BH : OFF_AH) + (lr * LDS_PAD + lh * 8) * 2;
    const uint32_t smL0 = sb + (ab ? OFF_BL : OFF_AL) + (lr * LDS_PAD + lh * 8) * 2;

    // compute mapping: 16 warps = 4m x 4n, warp tile 32x32
    const int wid = t >> 5;
    const int wm = wid >> 2;
    const int wn = wid & 3;
    const int lane = t & 31;
    const int qr = lane >> 2;
    const int qc = (lane & 3) * 2;

    float acc[2][4][4];
    #pragma unroll
    for (int i = 0; i < 2; i++)
        #pragma unroll
        for (int j = 0; j < 4; j++)
            #pragma unroll
            for (int r = 0; r < 4; r++) acc[i][j][r] = 0.f;

    const int NSTEP = K2 / BK;   // 1296

    // prologue: issue stages 0 and 1
    #pragma unroll
    for (int p = 0; p < 2; p++) {
        uint32_t so = p * STG_BYTES;
        CP_ASYNC16(smH0 + so, gH + p * BK);
        CP_ASYNC16(smL0 + so, gL + p * BK);
        CP_COMMIT();
    }
    CP_WAIT1();
    __syncthreads();

    for (int s = 0; s < NSTEP; s++) {
        const int buf = s - (s / 3) * 3;          // s % 3
        // issue stage s+2
        if (s + 2 < NSTEP) {
            int nb = s + 2 - ((s + 2) / 3) * 3;
            uint32_t so = nb * STG_BYTES;
            CP_ASYNC16(smH0 + so, gH + (s + 2) * BK);
            CP_ASYNC16(smL0 + so, gL + (s + 2) * BK);
        }
        CP_COMMIT();

        // compute on stage buf
        {
            const __nv_bfloat16* AH = (const __nv_bfloat16*)(smem + OFF_AH + buf * STG_BYTES);
            const __nv_bfloat16* AL = (const __nv_bfloat16*)(smem + OFF_AL + buf * STG_BYTES);
            const __nv_bfloat16* BH = (const __nv_bfloat16*)(smem + OFF_BH + buf * STG_BYTES);
            const __nv_bfloat16* BL = (const __nv_bfloat16*)(smem + OFF_BL + buf * STG_BYTES);
            uint32_t ah[2][4], al[2][4], bh[4][2], bl[4][2];
            #pragma unroll
            for (int i = 0; i < 2; i++) {
                int r0 = (wm * 32 + i * 16 + qr) * LDS_PAD;
                int r8 = r0 + 8 * LDS_PAD;
                ah[i][0] = *(const uint32_t*)(AH + r0 + qc);
                ah[i][1] = *(const uint32_t*)(AH + r8 + qc);
                ah[i][2] = *(const uint32_t*)(AH + r0 + qc + 8);
                ah[i][3] = *(const uint32_t*)(AH + r8 + qc + 8);
                al[i][0] = *(const uint32_t*)(AL + r0 + qc);
                al[i][1] = *(const uint32_t*)(AL + r8 + qc);
                al[i][2] = *(const uint32_t*)(AL + r0 + qc + 8);
                al[i][3] = *(const uint32_t*)(AL + r8 + qc + 8);
            }
            #pragma unroll
            for (int j = 0; j < 4; j++) {
                int nr = (wn * 32 + j * 8 + qr) * LDS_PAD;
                bh[j][0] = *(const uint32_t*)(BH + nr + qc);
                bh[j][1] = *(const uint32_t*)(BH + nr + qc + 8);
                bl[j][0] = *(const uint32_t*)(BL + nr + qc);
                bl[j][1] = *(const uint32_t*)(BL + nr + qc + 8);
            }
            #pragma unroll
            for (int i = 0; i < 2; i++)
                #pragma unroll
                for (int j = 0; j < 4; j++) {
                    mma_bf16(acc[i][j][0], acc[i][j][1], acc[i][j][2], acc[i][j][3],
                             ah[i][0], ah[i][1], ah[i][2], ah[i][3], bh[j][0], bh[j][1]);
                    mma_bf16(acc[i][j][0], acc[i][j][1], acc[i][j][2], acc[i][j][3],
                             ah[i][0], ah[i][1], ah[i][2], ah[i][3], bl[j][0], bl[j][1]);
                    mma_bf16(acc[i][j][0], acc[i][j][1], acc[i][j][2], acc[i][j][3],
                             al[i][0], al[i][1], al[i][2], al[i][3], bh[j][0], bh[j][1]);
                }
        }

        CP_WAIT1();
        __syncthreads();
    }

    // epilogue
    #pragma unroll
    for (int i = 0; i < 2; i++) {
        #pragma unroll
        for (int j = 0; j < 4; j++) {
            int r = m0 + wm * 32 + i * 16 + qr;
            int c = n0 + wn * 32 + j * 8 + qc;
            #pragma unroll
            for (int rr = 0; rr < 2; rr++) {
                int m = r + rr * 8;
                int b = m / 36, sidx = m - b * 36;
                float* op = out + (size_t)b * FLAT + sidx;
                op[(c + 0) * 36] = acc[i][j][rr * 2 + 0] + bias[c + 0];
                op[(c + 1) * 36] = acc[i][j][rr * 2 + 1] + bias[c + 1];
            }
        }
    }
}

// ---------------- Squash u ----------------
__global__ void squash_u_kernel(const float* __restrict__ c2, float* __restrict__ u) {
    int i = blockIdx.x * 256 + threadIdx.x;
    if (i >= BATCH * ROUTES) return;
    const float4* p = reinterpret_cast<const float4*>(c2 + (size_t)i * 8);
    float4 a = p[0], b = p[1];
    float sn = a.x*a.x + a.y*a.y + a.z*a.z + a.w*a.w
             + b.x*b.x + b.y*b.y + b.z*b.z + b.w*b.w + 1e-7f;
    float sc = sqrtf(sn) / (1.f + sn);
    float4 oa = make_float4(a.x*sc, a.y*sc, a.z*sc, a.w*sc);
    float4 ob = make_float4(b.x*sc, b.y*sc, b.z*sc, b.w*sc);
    float4* q = reinterpret_cast<float4*>(u + (size_t)i * 8);
    q[0] = oa; q[1] = ob;
}

// ---------------- u_hat -> layout [b][k][r][o] ----------------
__global__ void uhat_kernel(const float* __restrict__ W, const float* __restrict__ u,
                            float* __restrict__ uhat) {
    __shared__ float Wsm[1280];
    __shared__ float usm[256];
    int r = blockIdx.x;
    int bg = blockIdx.y;
    for (int i = threadIdx.x; i < 1280; i += 256) Wsm[i] = W[(size_t)r * 1280 + i];
    {
        int i = threadIdx.x;
        int bb = bg * 32 + (i >> 3);
        usm[i] = u[(size_t)bb * FLAT + r * 8 + (i & 7)];
    }
    __syncthreads();
    for (int i = threadIdx.x; i < 5120; i += 256) {
        int bi = i / 160, ko = i - bi * 160;
        const float* wp = &Wsm[ko * 8];
        const float* up = &usm[bi * 8];
        float acc = 0.f;
        #pragma unroll
        for (int c = 0; c < 8; c++) acc += wp[c] * up[c];
        int k = ko >> 4, o = ko & 15;
        uhat[(((size_t)(bg * 32 + bi) * NCAPS + k) * ROUTES + r) * 16 + o] = acc;
    }
}

// ---------------- Routing ----------------
__global__ void zero_bij_kernel(float* __restrict__ bij) {
    int i = blockIdx.x * 256 + threadIdx.x;
    if (i < ROUTES * NCAPS) bij[i] = 0.f;
}

__global__ void softmax_routes_kernel(const float* __restrict__ b, float* __restrict__ c) {
    int k = blockIdx.x;
    __shared__ float red[256];
    int tid = threadIdx.x;
    float m = -1e30f;
    for (int r = tid; r < ROUTES; r += 256) m = fmaxf(m, b[r * 10 + k]);
    red[tid] = m; __syncthreads();
    for (int s = 128; s > 0; s >>= 1) {
        if (tid < s) red[tid] = fmaxf(red[tid], red[tid + s]);
        __syncthreads();
    }
    m = red[0]; __syncthreads();
    float sum = 0.f;
    for (int r = tid; r < ROUTES; r += 256) sum += expf(b[r * 10 + k] - m);
    red[tid] = sum; __syncthreads();
    for (int s = 128; s > 0; s >>= 1) {
        if (tid < s) red[tid] += red[tid + s];
        __syncthreads();
    }
    float inv = 1.f / red[0];
    for (int r = tid; r < ROUTES; r += 256) c[r * 10 + k] = expf(b[r * 10 + k] - m) * inv;
}

__global__ void sv_kernel(const float* __restrict__ cij, const float* __restrict__ uhat,
                          float* __restrict__ v) {
    int b = blockIdx.x, k = blockIdx.y;
    int tid = threadIdx.x;   // 128
    __shared__ float cs[ROUTES];
    __shared__ float4 red[128];
    for (int i = tid; i < ROUTES; i += 128) cs[i] = cij[i * 10 + k];
    __syncthreads();
    const float4* base = reinterpret_cast<const float4*>(
        uhat + ((size_t)(b * NCAPS + k)) * ROUTES * 16);
    int q = tid & 3, rr = tid >> 2;
    float4 acc = make_float4(0.f, 0.f, 0.f, 0.f);
    for (int r0 = 0; r0 < ROUTES; r0 += 32) {
        int r = r0 + rr;
        float c = cs[r];
        float4 x = base[r * 4 + q];
        acc.x += c * x.x; acc.y += c * x.y; acc.z += c * x.z; acc.w += c * x.w;
    }
    red[tid] = acc; __syncthreads();
    for (int s = 64; s >= 4; s >>= 1) {
        if (tid < s) {
            float4 o = red[tid + s];
            red[tid].x += o.x; red[tid].y += o.y; red[tid].z += o.z; red[tid].w += o.w;
        }
        __syncthreads();
    }
    if (tid == 0) {
        float sv16[16]; float sn = 0.f;
        #pragma unroll
        for (int q2 = 0; q2 < 4; q2++) {
            float4 x = red[q2];
            sv16[q2*4+0] = x.x; sv16[q2*4+1] = x.y; sv16[q2*4+2] = x.z; sv16[q2*4+3] = x.w;
            sn += x.x*x.x + x.y*x.y + x.z*x.z + x.w*x.w;
        }
        float sc = sqrtf(sn) / (1.f + sn);
        #pragma unroll
        for (int o = 0; o < 16; o++) v[(b * NCAPS + k) * 16 + o] = sv16[o] * sc;
    }
}

__global__ void agree_kernel(const float* __restrict__ uhat, const float* __restrict__ v,
                             float* __restrict__ bij) {
    int k = blockIdx.x;
    int r0 = blockIdx.y * 64;
    int tid = threadIdx.x;   // 256
    __shared__ __align__(16) float4 vs4[BATCH * 4];
    for (int i = tid; i < BATCH * 4; i += 256) {
        int b = i >> 2, q2 = i & 3;
        vs4[i] = *reinterpret_cast<const float4*>(v + (b * NCAPS + k) * 16 + q2 * 4);
    }
    __syncthreads();
    int q = tid & 3, rr = tid >> 2;
    int r = r0 + rr;
    const float4* U = reinterpret_cast<const float4*>(uhat);
    float acc = 0.f;
    for (int b = 0; b < BATCH; b++) {
        float4 x = U[((size_t)(b * NCAPS + k) * ROUTES + r) * 4 + q];
        float4 vv = vs4[b * 4 + q];
        acc += x.x*vv.x + x.y*vv.y + x.z*vv.z + x.w*vv.w;
    }
    acc += __shfl_down_sync(0xffffffffu, acc, 2);
    acc += __shfl_down_sync(0xffffffffu, acc, 1);
    if (q == 0) bij[r * 10 + k] += acc * (1.f / (float)BATCH);
}

// ---------------- Mask / argmax ----------------
__global__ void mask_kernel(const float* __restrict__ v, float* __restrict__ out_obj,
                            float* __restrict__ out_mask, int* __restrict__ best) {
    int b = blockIdx.x * blockDim.x + threadIdx.x;
    if (b >= BATCH) return;
    const float* vb = v + b * 160;
    float bestn = -1.f; int bi = 0;
    #pragma unroll
    for (int k = 0; k < 10; k++) {
        float sn = 0.f;
        #pragma unroll
        for (int o = 0; o < 16; o++) { float t = vb[k * 16 + o]; sn += t * t; }
        if (sn > bestn) { bestn = sn; bi = k; }
    }
    best[b] = bi;
    for (int i = 0; i < 160; i++) out_obj[b * 160 + i] = vb[i];
    #pragma unroll
    for (int k = 0; k < 10; k++) out_mask[b * 10 + k] = (k == bi) ? 1.f : 0.f;
}

// ---------------- Decoder ----------------
__global__ void dec1_kernel(const float* __restrict__ v, const int* __restrict__ best,
                            const float* __restrict__ w1, const float* __restrict__ b1,
                            float* __restrict__ h1) {
    int b = blockIdx.x;
    int j = threadIdx.x;
    __shared__ float vs[16];
    int bi = best[b];
    if (threadIdx.x < 16) vs[threadIdx.x] = v[b * 160 + bi * 16 + threadIdx.x];
    __syncthreads();
    float acc = b1[j];
    #pragma unroll
    for (int o = 0; o < 16; o++) acc += vs[o] * w1[(bi * 16 + o) * 512 + j];
    h1[b * 512 + j] = fmaxf(acc, 0.f);
}

template<int ACT>
__global__ void gemm_act_kernel(const float* __restrict__ A, const float* __restrict__ W,
                                const float* __restrict__ bias, float* __restrict__ C,
                                int M, int N, int K) {
    __shared__ float As[16][64];
    __shared__ float Bs[16][64];
    int tid = threadIdx.x;
    int m0 = blockIdx.y * 64, n0 = blockIdx.x * 64;
    int ty = tid >> 4, tx = tid & 15;
    float acc[4][4];
    #pragma unroll
    for (int i = 0; i < 4; i++)
        #pragma unroll
        for (int j = 0; j < 4; j++) acc[i][j] = 0.f;

    int lam = tid >> 2;
    int lak = (tid & 3) * 4;
    int lbk = tid >> 4;
    int lbn = (tid & 15) * 4;

    for (int k0 = 0; k0 < K; k0 += 16) {
        float4 av = *reinterpret_cast<const float4*>(A + (size_t)(m0 + lam) * K + k0 + lak);
        As[lak + 0][lam] = av.x; As[lak + 1][lam] = av.y;
        As[lak + 2][lam] = av.z; As[lak + 3][lam] = av.w;
        #pragma unroll
        for (int i = 0; i < 4; i++) {
            int n = n0 + lbn + i;
            Bs[lbk][lbn + i] = (n < N) ? W[(size_t)(k0 + lbk) * N + n] : 0.f;
        }
        __syncthreads();
        #pragma unroll
        for (int kk = 0; kk < 16; kk++) {
            float af[4], bf[4];
            #pragma unroll
            for (int i = 0; i < 4; i++) af[i] = As[kk][ty * 4 + i];
            #pragma unroll
            for (int j = 0; j < 4; j++) bf[j] = Bs[kk][tx * 4 + j];
            #pragma unroll
            for (int i = 0; i < 4; i++)
                #pragma unroll
                for (int j = 0; j < 4; j++)
                    acc[i][j] += af[i] * bf[j];
        }
        __syncthreads();
    }
    #pragma unroll
    for (int i = 0; i < 4; i++) {
        int m = m0 + ty * 4 + i;
        #pragma unroll
        for (int j = 0; j < 4; j++) {
            int n = n0 + tx * 4 + j;
            if (n < N) {
                float x = acc[i][j] + bias[n];
                if (ACT == 0) x = fmaxf(x, 0.f);
                else          x = 1.f / (1.f + expf(-x));
                C[(size_t)m * N + n] = x;
            }
        }
    }
}

// ---------------- Host launcher ----------------
extern "C" void kernel_launch(void* const* d_in, const int* in_sizes, int n_in,
                              void* d_out, int out_size) {
    const float* image  = (const float*)d_in[0];
    const float* conv_w = (const float*)d_in[1];
    const float* conv_b = (const float*)d_in[2];
    const float* pc_w   = (const float*)d_in[3];
    const float* pc_b   = (const float*)d_in[4];
    const float* W_obj  = (const float*)d_in[5];
    const float* dec_w1 = (const float*)d_in[6];
    const float* dec_b1 = (const float*)d_in[7];
    const float* dec_w2 = (const float*)d_in[8];
    const float* dec_b2 = (const float*)d_in[9];
    const float* dec_w3 = (const float*)d_in[10];
    const float* dec_b3 = (const float*)d_in[11];

    float* out = (float*)d_out;
    float* out_obj  = out;
    float* out_rec  = out + BATCH * 160;
    float* out_mask = out + BATCH * (160 + 784);

    unsigned char* big = nullptr; cudaGetSymbolAddress((void**)&big, g_big);
    __nv_bfloat16* aimH = (__nv_bfloat16*)big;                       // live: im2col -> conv2
    __nv_bfloat16* aimL = (__nv_bfloat16*)(big + PLANE_ELEMS * 2);
    float*         uhat = (float*)big;                               // live after conv2
    uint32_t* x1p  = nullptr; cudaGetSymbolAddress((void**)&x1p,  g_x1p);
    __nv_bfloat16* bpH = nullptr; cudaGetSymbolAddress((void**)&bpH, g_bpH);
    __nv_bfloat16* bpL = nullptr; cudaGetSymbolAddress((void**)&bpL, g_bpL);
    int*      koff = nullptr; cudaGetSymbolAddress((void**)&koff, g_kofft);
    float* c2   = nullptr; cudaGetSymbolAddress((void**)&c2,   g_c2);
    float* u    = nullptr; cudaGetSymbolAddress((void**)&u,    g_u);
    float* bij  = nullptr; cudaGetSymbolAddress((void**)&bij,  g_bij);
    float* cij  = nullptr; cudaGetSymbolAddress((void**)&cij,  g_cij);
    float* v    = nullptr; cudaGetSymbolAddress((void**)&v,    g_v);
    int*   best = nullptr; cudaGetSymbolAddress((void**)&best, g_best);
    float* h1   = nullptr; cudaGetSymbolAddress((void**)&h1,   g_h1);
    float* h2   = nullptr; cudaGetSymbolAddress((void**)&h2,   g_h2);

    static bool attr_set = false;
    if (!attr_set) {
        cudaFuncSetAttribute(conv2_mma_kernel,
                             cudaFuncAttributeMaxDynamicSharedMemorySize, SMEM_CONV2);
        attr_set = true;
    }

    // 0) pre-split B + offset table
    bsplit_kernel<<<(N2 * K2 + 1023) / 1024, 1024>>>(pc_w, bpH, bpL);
    kofft_kernel<<<(K2 + 255) / 256, 256>>>(koff);
    // 1) conv1 + relu -> packed bf16 split
    conv1_kernel<<<dim3(BATCH, 8), 256>>>(image, conv_w, conv_b, x1p);
    // 2) im2col -> H/L planes
    im2col_kernel<<<M2, 256>>>(x1p, koff, aimH, aimL);
    // 3) conv2: cp.async pipelined split-bf16 MMA GEMM
    conv2_mma_kernel<<<dim3(N2 / 128, M2 / 128), 512, SMEM_CONV2>>>(aimH, aimL, bpH, bpL, pc_b, c2);
    // 4) squash -> u
    squash_u_kernel<<<(BATCH * ROUTES + 255) / 256, 256>>>(c2, u);
    // 5) u_hat ([b][k][r][o]) — reuses big buffer
    uhat_kernel<<<dim3(ROUTES, BATCH / 32), 256>>>(W_obj, u, uhat);
    // 6) routing (3 iterations)
    zero_bij_kernel<<<(ROUTES * NCAPS + 255) / 256, 256>>>(bij);
    for (int it = 0; it < 3; it++) {
        softmax_routes_kernel<<<NCAPS, 256>>>(bij, cij);
        sv_kernel<<<dim3(BATCH, NCAPS), 128>>>(cij, uhat, v);
        if (it < 2)
            agree_kernel<<<dim3(NCAPS, ROUTES / 64), 256>>>(uhat, v, bij);
    }
    // 7) mask + obj output
    mask_kernel<<<2, 256>>>(v, out_obj, out_mask, best);
    // 8) decoder
    dec1_kernel<<<BATCH, 512>>>(v, best, dec_w1, dec_b1, h1);
    gemm_act_kernel<0><<<dim3(1024 / 64, BATCH / 64), 256>>>(h1, dec_w2, dec_b2, h2, BATCH, 1024, 512);
    gemm_act_kernel<1><<<dim3((784 + 63) / 64, BATCH / 64), 256>>>(h2, dec_w3, dec_b3, out_rec, BATCH, 784, 1024);
}

// round 14
// speedup vs baseline: 1.1571x; 1.1571x over previous
#include <cuda_runtime.h>
#include <cuda_bf16.h>
#include <stdint.h>
#include <math.h>

// ---------------- Problem constants ----------------
#define BATCH 512
#define C1 256
#define ROUTES 1152
#define NCAPS 10
#define CAPDIM 16
#define M2 (BATCH*36)     // 18432
#define K2 20736          // 256*81
#define N2 256
#define FLAT 9216

// ---------------- Device scratch ----------------
// g_big: aim (packed im2col, live until conv2) then uhat (after conv2).
#define BIG_BYTES ((size_t)M2 * K2 * 4)
__device__ __align__(128) unsigned char g_big[BIG_BYTES];
__device__ __align__(16) uint32_t g_x1p[BATCH*C1*20*20];
__device__ __align__(16) uint32_t g_bp[(size_t)N2*K2];
__device__ __align__(16) int      g_kofft[K2];
__device__ __align__(16) float g_c2[BATCH*FLAT];
__device__ __align__(16) float g_u[BATCH*FLAT];
__device__ __align__(16) float g_bij[ROUTES*NCAPS];
__device__ __align__(16) float g_cij[ROUTES*NCAPS];
__device__ __align__(16) float g_v[BATCH*NCAPS*CAPDIM];
__device__ int   g_best[BATCH];
__device__ __align__(16) float g_h1[BATCH*512];
__device__ __align__(16) float g_h2[BATCH*1024];

// ---------------- pack helper ----------------
__device__ __forceinline__ uint32_t pack_split(float x) {
    __nv_bfloat16 h = __float2bfloat16(x);
    __nv_bfloat16 l = __float2bfloat16(x - __bfloat162float(h));
    return (uint32_t)__bfloat16_as_ushort(h) | ((uint32_t)__bfloat16_as_ushort(l) << 16);
}

__global__ void bsplit_kernel(const float* __restrict__ w, uint32_t* __restrict__ bp) {
    int i = blockIdx.x * 1024 + threadIdx.x;
    if (i < N2 * K2) bp[i] = pack_split(w[i]);
}

__global__ void kofft_kernel(int* __restrict__ tab) {
    int k = blockIdx.x * 256 + threadIdx.x;
    if (k >= K2) return;
    int ci = k / 81, rem = k - ci * 81;
    int ky = rem / 9, kx = rem - ky * 9;
    tab[k] = ci * 400 + ky * 20 + kx;
}

// ---------------- Conv1 -> packed split ----------------
__global__ void conv1_kernel(const float* __restrict__ img, const float* __restrict__ w,
                             const float* __restrict__ bias, uint32_t* __restrict__ x1p) {
    __shared__ float ism[784];
    __shared__ float wsm[32 * 81];
    int b = blockIdx.x, g = blockIdx.y;
    for (int i = threadIdx.x; i < 784; i += 256) ism[i] = img[b * 784 + i];
    for (int i = threadIdx.x; i < 2592; i += 256) wsm[i] = w[g * 2592 + i];
    __syncthreads();
    for (int idx = threadIdx.x; idx < 32 * 400; idx += 256) {
        int cl = idx / 400, pix = idx - cl * 400;
        int y = pix / 20, x = pix - y * 20;
        const float* wp = &wsm[cl * 81];
        float acc = bias[g * 32 + cl];
        #pragma unroll
        for (int ky = 0; ky < 9; ky++) {
            const float* irow = &ism[(y + ky) * 28 + x];
            #pragma unroll
            for (int kx = 0; kx < 9; kx++)
                acc += irow[kx] * wp[ky * 9 + kx];
        }
        x1p[(size_t)b * 102400 + (size_t)(g * 32 + cl) * 400 + pix] = pack_split(fmaxf(acc, 0.f));
    }
}

// ---------------- im2col: A[m][k] packed ----------------
__global__ void im2col_kernel(const uint32_t* __restrict__ x1p, const int* __restrict__ kofft,
                              uint32_t* __restrict__ aim) {
    int m = blockIdx.x;
    int b = m / 36, s = m - b * 36;
    int oy = s / 6, ox = s - oy * 6;
    const uint32_t* base = x1p + (size_t)b * 102400 + oy * 40 + ox * 2;
    uint32_t* dst = aim + (size_t)m * K2;
    for (int k = threadIdx.x; k < K2; k += 256)
        dst[k] = base[kofft[k]];
}

// ---------------- Conv2: split-bf16 MMA, BK=32, 648 stages ----------------
#define BK 32
#define RS 40   // smem row stride in bf16 elems (32 + 8 pad), conflict-free

#define ARR_STG (128 * RS * 2)          // bytes per array per stage = 10240
#define SMEM_CONV2 (8 * ARR_STG)        // 4 arrays x 2 stages = 81920

__device__ __forceinline__ void mma_bf16(float& c0, float& c1, float& c2, float& c3,
                                         uint32_t a0, uint32_t a1, uint32_t a2, uint32_t a3,
                                         uint32_t b0, uint32_t b1) {
    asm volatile(
        "mma.sync.aligned.m16n8k16.row.col.f32.bf16.bf16.f32 "
        "{%0,%1,%2,%3}, {%4,%5,%6,%7}, {%8,%9}, {%0,%1,%2,%3};\n"
        : "+f"(c0), "+f"(c1), "+f"(c2), "+f"(c3)
        : "r"(a0), "r"(a1), "r"(a2), "r"(a3), "r"(b0), "r"(b1));
}

__global__ __launch_bounds__(512, 1)
void conv2_mma_kernel(const uint32_t* __restrict__ aim, const uint32_t* __restrict__ bp,
                      const float* __restrict__ bias, float* __restrict__ out) {
    extern __shared__ char smem[];
    // layout: AsH[2] | AsL[2] | BsH[2] | BsL[2], each stage ARR_STG bytes
    char* const pAH = smem;
    char* const pAL = smem + 2 * ARR_STG;
    char* const pBH = smem + 4 * ARR_STG;
    char* const pBL = smem + 6 * ARR_STG;

    const int t = threadIdx.x;
    const int m0 = blockIdx.y * 128;
    const int n0 = blockIdx.x * 128;

    // loader: row = t>>2 (0..127), k-eighth = (t&3)*8
    const int lr = t >> 2;
    const int kq = (t & 3) * 8;

    const uint32_t* abase = aim + (size_t)(m0 + lr) * K2 + kq;
    const uint32_t* bbase = bp + (size_t)(n0 + lr) * K2 + kq;
    const int sa = lr * RS + kq;   // bf16 elem offset (byte = *2, 16B aligned)

    // compute mapping: 16 warps = 4m x 4n, warp tile 32x32
    const int wid = t >> 5;
    const int wm = wid >> 2;
    const int wn = wid & 3;
    const int lane = t & 31;
    const int qr = lane >> 2;
    const int qc = (lane & 3) * 2;

    float acc[2][4][4];
    #pragma unroll
    for (int i = 0; i < 2; i++)
        #pragma unroll
        for (int j = 0; j < 4; j++)
            #pragma unroll
            for (int r = 0; r < 4; r++) acc[i][j][r] = 0.f;

    uint4 ua0, ua1, ub0, ub1;

    // helper lambda-free store of a prefetched chunk into stage `st`
    #define STORE_STAGE(st) do { \
        uint4 h4, l4; \
        h4.x = __byte_perm(ua0.x, ua0.y, 0x5410); h4.y = __byte_perm(ua0.z, ua0.w, 0x5410); \
        h4.z = __byte_perm(ua1.x, ua1.y, 0x5410); h4.w = __byte_perm(ua1.z, ua1.w, 0x5410); \
        l4.x = __byte_perm(ua0.x, ua0.y, 0x7632); l4.y = __byte_perm(ua0.z, ua0.w, 0x7632); \
        l4.z = __byte_perm(ua1.x, ua1.y, 0x7632); l4.w = __byte_perm(ua1.z, ua1.w, 0x7632); \
        *reinterpret_cast<uint4*>(pAH + (st) * ARR_STG + sa * 2) = h4; \
        *reinterpret_cast<uint4*>(pAL + (st) * ARR_STG + sa * 2) = l4; \
        h4.x = __byte_perm(ub0.x, ub0.y, 0x5410); h4.y = __byte_perm(ub0.z, ub0.w, 0x5410); \
        h4.z = __byte_perm(ub1.x, ub1.y, 0x5410); h4.w = __byte_perm(ub1.z, ub1.w, 0x5410); \
        l4.x = __byte_perm(ub0.x, ub0.y, 0x7632); l4.y = __byte_perm(ub0.z, ub0.w, 0x7632); \
        l4.z = __byte_perm(ub1.x, ub1.y, 0x7632); l4.w = __byte_perm(ub1.z, ub1.w, 0x7632); \
        *reinterpret_cast<uint4*>(pBH + (st) * ARR_STG + sa * 2) = h4; \
        *reinterpret_cast<uint4*>(pBL + (st) * ARR_STG + sa * 2) = l4; \
    } while (0)

    // prologue: stage 0
    ua0 = *reinterpret_cast<const uint4*>(abase);
    ua1 = *reinterpret_cast<const uint4*>(abase + 4);
    ub0 = *reinterpret_cast<const uint4*>(bbase);
    ub1 = *reinterpret_cast<const uint4*>(bbase + 4);
    STORE_STAGE(0);
    __syncthreads();

    const int NSTEP = K2 / BK;   // 648
    for (int s = 0; s < NSTEP; s++) {
        const int cur = s & 1;
        const bool more = (s + 1 < NSTEP);
        if (more) {
            const uint32_t* ap = abase + (s + 1) * BK;
            const uint32_t* bpp2 = bbase + (s + 1) * BK;
            ua0 = *reinterpret_cast<const uint4*>(ap);
            ua1 = *reinterpret_cast<const uint4*>(ap + 4);
            ub0 = *reinterpret_cast<const uint4*>(bpp2);
            ub1 = *reinterpret_cast<const uint4*>(bpp2 + 4);
        }

        // compute: 2 k-steps of 16
        {
            const __nv_bfloat16* AH = (const __nv_bfloat16*)(pAH + cur * ARR_STG);
            const __nv_bfloat16* AL = (const __nv_bfloat16*)(pAL + cur * ARR_STG);
            const __nv_bfloat16* BH = (const __nv_bfloat16*)(pBH + cur * ARR_STG);
            const __nv_bfloat16* BL = (const __nv_bfloat16*)(pBL + cur * ARR_STG);
            #pragma unroll
            for (int ks = 0; ks < 2; ks++) {
                const int kk0 = ks * 16;
                uint32_t ah[2][4], al[2][4], bh[4][2], bl[4][2];
                #pragma unroll
                for (int i = 0; i < 2; i++) {
                    int r0 = (wm * 32 + i * 16 + qr) * RS + kk0;
                    int r8 = r0 + 8 * RS;
                    ah[i][0] = *(const uint32_t*)(AH + r0 + qc);
                    ah[i][1] = *(const uint32_t*)(AH + r8 + qc);
                    ah[i][2] = *(const uint32_t*)(AH + r0 + qc + 8);
                    ah[i][3] = *(const uint32_t*)(AH + r8 + qc + 8);
                    al[i][0] = *(const uint32_t*)(AL + r0 + qc);
                    al[i][1] = *(const uint32_t*)(AL + r8 + qc);
                    al[i][2] = *(const uint32_t*)(AL + r0 + qc + 8);
                    al[i][3] = *(const uint32_t*)(AL + r8 + qc + 8);
                }
                #pragma unroll
                for (int j = 0; j < 4; j++) {
                    int nr = (wn * 32 + j * 8 + qr) * RS + kk0;
                    bh[j][0] = *(const uint32_t*)(BH + nr + qc);
                    bh[j][1] = *(const uint32_t*)(BH + nr + qc + 8);
                    bl[j][0] = *(const uint32_t*)(BL + nr + qc);
                    bl[j][1] = *(const uint32_t*)(BL + nr + qc + 8);
                }
                #pragma unroll
                for (int i = 0; i < 2; i++)
                    #pragma unroll
                    for (int j = 0; j < 4; j++) {
                        mma_bf16(acc[i][j][0], acc[i][j][1], acc[i][j][2], acc[i][j][3],
                                 ah[i][0], ah[i][1], ah[i][2], ah[i][3], bh[j][0], bh[j][1]);
                        mma_bf16(acc[i][j][0], acc[i][j][1], acc[i][j][2], acc[i][j][3],
                                 ah[i][0], ah[i][1], ah[i][2], ah[i][3], bl[j][0], bl[j][1]);
                        mma_bf16(acc[i][j][0], acc[i][j][1], acc[i][j][2], acc[i][j][3],
                                 al[i][0], al[i][1], al[i][2], al[i][3], bh[j][0], bh[j][1]);
                    }
            }
        }

        if (more) STORE_STAGE(cur ^ 1);
        __syncthreads();
    }
    #undef STORE_STAGE

    // epilogue: C[m][n] -> out[b*FLAT + n*36 + s] + bias[n]
    #pragma unroll
    for (int i = 0; i < 2; i++) {
        #pragma unroll
        for (int j = 0; j < 4; j++) {
            int r = m0 + wm * 32 + i * 16 + qr;
            int c = n0 + wn * 32 + j * 8 + qc;
            #pragma unroll
            for (int rr = 0; rr < 2; rr++) {
                int m = r + rr * 8;
                int b = m / 36, sidx = m - b * 36;
                float* op = out + (size_t)b * FLAT + sidx;
                op[(c + 0) * 36] = acc[i][j][rr * 2 + 0] + bias[c + 0];
                op[(c + 1) * 36] = acc[i][j][rr * 2 + 1] + bias[c + 1];
            }
        }
    }
}

// ---------------- Squash u ----------------
__global__ void squash_u_kernel(const float* __restrict__ c2, float* __restrict__ u) {
    int i = blockIdx.x * 256 + threadIdx.x;
    if (i >= BATCH * ROUTES) return;
    const float4* p = reinterpret_cast<const float4*>(c2 + (size_t)i * 8);
    float4 a = p[0], b = p[1];
    float sn = a.x*a.x + a.y*a.y + a.z*a.z + a.w*a.w
             + b.x*b.x + b.y*b.y + b.z*b.z + b.w*b.w + 1e-7f;
    float sc = sqrtf(sn) / (1.f + sn);
    float4 oa = make_float4(a.x*sc, a.y*sc, a.z*sc, a.w*sc);
    float4 ob = make_float4(b.x*sc, b.y*sc, b.z*sc, b.w*sc);
    float4* q = reinterpret_cast<float4*>(u + (size_t)i * 8);
    q[0] = oa; q[1] = ob;
}

// ---------------- u_hat -> layout [b][k][r][o] ----------------
__global__ void uhat_kernel(const float* __restrict__ W, const float* __restrict__ u,
                            float* __restrict__ uhat) {
    __shared__ float Wsm[1280];
    __shared__ float usm[256];
    int r = blockIdx.x;
    int bg = blockIdx.y;
    for (int i = threadIdx.x; i < 1280; i += 256) Wsm[i] = W[(size_t)r * 1280 + i];
    {
        int i = threadIdx.x;
        int bb = bg * 32 + (i >> 3);
        usm[i] = u[(size_t)bb * FLAT + r * 8 + (i & 7)];
    }
    __syncthreads();
    for (int i = threadIdx.x; i < 5120; i += 256) {
        int bi = i / 160, ko = i - bi * 160;
        const float* wp = &Wsm[ko * 8];
        const float* up = &usm[bi * 8];
        float acc = 0.f;
        #pragma unroll
        for (int c = 0; c < 8; c++) acc += wp[c] * up[c];
        int k = ko >> 4, o = ko & 15;
        uhat[(((size_t)(bg * 32 + bi) * NCAPS + k) * ROUTES + r) * 16 + o] = acc;
    }
}

// ---------------- Routing ----------------
__global__ void zero_bij_kernel(float* __restrict__ bij) {
    int i = blockIdx.x * 256 + threadIdx.x;
    if (i < ROUTES * NCAPS) bij[i] = 0.f;
}

__global__ void softmax_routes_kernel(const float* __restrict__ b, float* __restrict__ c) {
    int k = blockIdx.x;
    __shared__ float red[256];
    int tid = threadIdx.x;
    float m = -1e30f;
    for (int r = tid; r < ROUTES; r += 256) m = fmaxf(m, b[r * 10 + k]);
    red[tid] = m; __syncthreads();
    for (int s = 128; s > 0; s >>= 1) {
        if (tid < s) red[tid] = fmaxf(red[tid], red[tid + s]);
        __syncthreads();
    }
    m = red[0]; __syncthreads();
    float sum = 0.f;
    for (int r = tid; r < ROUTES; r += 256) sum += expf(b[r * 10 + k] - m);
    red[tid] = sum; __syncthreads();
    for (int s = 128; s > 0; s >>= 1) {
        if (tid < s) red[tid] += red[tid + s];
        __syncthreads();
    }
    float inv = 1.f / red[0];
    for (int r = tid; r < ROUTES; r += 256) c[r * 10 + k] = expf(b[r * 10 + k] - m) * inv;
}

__global__ void sv_kernel(const float* __restrict__ cij, const float* __restrict__ uhat,
                          float* __restrict__ v) {
    int b = blockIdx.x, k = blockIdx.y;
    int tid = threadIdx.x;   // 128
    __shared__ float cs[ROUTES];
    __shared__ float4 red[128];
    for (int i = tid; i < ROUTES; i += 128) cs[i] = cij[i * 10 + k];
    __syncthreads();
    const float4* base = reinterpret_cast<const float4*>(
        uhat + ((size_t)(b * NCAPS + k)) * ROUTES * 16);
    int q = tid & 3, rr = tid >> 2;
    float4 acc = make_float4(0.f, 0.f, 0.f, 0.f);
    for (int r0 = 0; r0 < ROUTES; r0 += 32) {
        int r = r0 + rr;
        float c = cs[r];
        float4 x = base[r * 4 + q];
        acc.x += c * x.x; acc.y += c * x.y; acc.z += c * x.z; acc.w += c * x.w;
    }
    red[tid] = acc; __syncthreads();
    for (int s = 64; s >= 4; s >>= 1) {
        if (tid < s) {
            float4 o = red[tid + s];
            red[tid].x += o.x; red[tid].y += o.y; red[tid].z += o.z; red[tid].w += o.w;
        }
        __syncthreads();
    }
    if (tid == 0) {
        float sv16[16]; float sn = 0.f;
        #pragma unroll
        for (int q2 = 0; q2 < 4; q2++) {
            float4 x = red[q2];
            sv16[q2*4+0] = x.x; sv16[q2*4+1] = x.y; sv16[q2*4+2] = x.z; sv16[q2*4+3] = x.w;
            sn += x.x*x.x + x.y*x.y + x.z*x.z + x.w*x.w;
        }
        float sc = sqrtf(sn) / (1.f + sn);
        #pragma unroll
        for (int o = 0; o < 16; o++) v[(b * NCAPS + k) * 16 + o] = sv16[o] * sc;
    }
}

__global__ void agree_kernel(const float* __restrict__ uhat, const float* __restrict__ v,
                             float* __restrict__ bij) {
    int k = blockIdx.x;
    int r0 = blockIdx.y * 64;
    int tid = threadIdx.x;   // 256
    __shared__ __align__(16) float4 vs4[BATCH * 4];
    for (int i = tid; i < BATCH * 4; i += 256) {
        int b = i >> 2, q2 = i & 3;
        vs4[i] = *reinterpret_cast<const float4*>(v + (b * NCAPS + k) * 16 + q2 * 4);
    }
    __syncthreads();
    int q = tid & 3, rr = tid >> 2;
    int r = r0 + rr;
    const float4* U = reinterpret_cast<const float4*>(uhat);
    float acc = 0.f;
    for (int b = 0; b < BATCH; b++) {
        float4 x = U[((size_t)(b * NCAPS + k) * ROUTES + r) * 4 + q];
        float4 vv = vs4[b * 4 + q];
        acc += x.x*vv.x + x.y*vv.y + x.z*vv.z + x.w*vv.w;
    }
    acc += __shfl_down_sync(0xffffffffu, acc, 2);
    acc += __shfl_down_sync(0xffffffffu, acc, 1);
    if (q == 0) bij[r * 10 + k] += acc * (1.f / (float)BATCH);
}

// ---------------- Mask / argmax ----------------
__global__ void mask_kernel(const float* __restrict__ v, float* __restrict__ out_obj,
                            float* __restrict__ out_mask, int* __restrict__ best) {
    int b = blockIdx.x * blockDim.x + threadIdx.x;
    if (b >= BATCH) return;
    const float* vb = v + b * 160;
    float bestn = -1.f; int bi = 0;
    #pragma unroll
    for (int k = 0; k < 10; k++) {
        float sn = 0.f;
        #pragma unroll
        for (int o = 0; o < 16; o++) { float t = vb[k * 16 + o]; sn += t * t; }
        if (sn > bestn) { bestn = sn; bi = k; }
    }
    best[b] = bi;
    for (int i = 0; i < 160; i++) out_obj[b * 160 + i] = vb[i];
    #pragma unroll
    for (int k = 0; k < 10; k++) out_mask[b * 10 + k] = (k == bi) ? 1.f : 0.f;
}

// ---------------- Decoder ----------------
__global__ void dec1_kernel(const float* __restrict__ v, const int* __restrict__ best,
                            const float* __restrict__ w1, const float* __restrict__ b1,
                            float* __restrict__ h1) {
    int b = blockIdx.x;
    int j = threadIdx.x;
    __shared__ float vs[16];
    int bi = best[b];
    if (threadIdx.x < 16) vs[threadIdx.x] = v[b * 160 + bi * 16 + threadIdx.x];
    __syncthreads();
    float acc = b1[j];
    #pragma unroll
    for (int o = 0; o < 16; o++) acc += vs[o] * w1[(bi * 16 + o) * 512 + j];
    h1[b * 512 + j] = fmaxf(acc, 0.f);
}

template<int ACT>
__global__ void gemm_act_kernel(const float* __restrict__ A, const float* __restrict__ W,
                                const float* __restrict__ bias, float* __restrict__ C,
                                int M, int N, int K) {
    __shared__ float As[16][64];
    __shared__ float Bs[16][64];
    int tid = threadIdx.x;
    int m0 = blockIdx.y * 64, n0 = blockIdx.x * 64;
    int ty = tid >> 4, tx = tid & 15;
    float acc[4][4];
    #pragma unroll
    for (int i = 0; i < 4; i++)
        #pragma unroll
        for (int j = 0; j < 4; j++) acc[i][j] = 0.f;

    int lam = tid >> 2;
    int lak = (tid & 3) * 4;
    int lbk = tid >> 4;
    int lbn = (tid & 15) * 4;

    for (int k0 = 0; k0 < K; k0 += 16) {
        float4 av = *reinterpret_cast<const float4*>(A + (size_t)(m0 + lam) * K + k0 + lak);
        As[lak + 0][lam] = av.x; As[lak + 1][lam] = av.y;
        As[lak + 2][lam] = av.z; As[lak + 3][lam] = av.w;
        #pragma unroll
        for (int i = 0; i < 4; i++) {
            int n = n0 + lbn + i;
            Bs[lbk][lbn + i] = (n < N) ? W[(size_t)(k0 + lbk) * N + n] : 0.f;
        }
        __syncthreads();
        #pragma unroll
        for (int kk = 0; kk < 16; kk++) {
            float af[4], bf[4];
            #pragma unroll
            for (int i = 0; i < 4; i++) af[i] = As[kk][ty * 4 + i];
            #pragma unroll
            for (int j = 0; j < 4; j++) bf[j] = Bs[kk][tx * 4 + j];
            #pragma unroll
            for (int i = 0; i < 4; i++)
                #pragma unroll
                for (int j = 0; j < 4; j++)
                    acc[i][j] += af[i] * bf[j];
        }
        __syncthreads();
    }
    #pragma unroll
    for (int i = 0; i < 4; i++) {
        int m = m0 + ty * 4 + i;
        #pragma unroll
        for (int j = 0; j < 4; j++) {
            int n = n0 + tx * 4 + j;
            if (n < N) {
                float x = acc[i][j] + bias[n];
                if (ACT == 0) x = fmaxf(x, 0.f);
                else          x = 1.f / (1.f + expf(-x));
                C[(size_t)m * N + n] = x;
            }
        }
    }
}

// ---------------- Host launcher ----------------
extern "C" void kernel_launch(void* const* d_in, const int* in_sizes, int n_in,
                              void* d_out, int out_size) {
    const float* image  = (const float*)d_in[0];
    const float* conv_w = (const float*)d_in[1];
    const float* conv_b = (const float*)d_in[2];
    const float* pc_w   = (const float*)d_in[3];
    const float* pc_b   = (const float*)d_in[4];
    const float* W_obj  = (const float*)d_in[5];
    const float* dec_w1 = (const float*)d_in[6];
    const float* dec_b1 = (const float*)d_in[7];
    const float* dec_w2 = (const float*)d_in[8];
    const float* dec_b2 = (const float*)d_in[9];
    const float* dec_w3 = (const float*)d_in[10];
    const float* dec_b3 = (const float*)d_in[11];

    float* out = (float*)d_out;
    float* out_obj  = out;
    float* out_rec  = out + BATCH * 160;
    float* out_mask = out + BATCH * (160 + 784);

    unsigned char* big = nullptr; cudaGetSymbolAddress((void**)&big, g_big);
    uint32_t* aim  = (uint32_t*)big;     // live: im2col -> conv2
    float*    uhat = (float*)big;        // live after conv2
    uint32_t* x1p  = nullptr; cudaGetSymbolAddress((void**)&x1p,  g_x1p);
    uint32_t* bpp  = nullptr; cudaGetSymbolAddress((void**)&bpp,  g_bp);
    int*      koff = nullptr; cudaGetSymbolAddress((void**)&koff, g_kofft);
    float* c2   = nullptr; cudaGetSymbolAddress((void**)&c2,   g_c2);
    float* u    = nullptr; cudaGetSymbolAddress((void**)&u,    g_u);
    float* bij  = nullptr; cudaGetSymbolAddress((void**)&bij,  g_bij);
    float* cij  = nullptr; cudaGetSymbolAddress((void**)&cij,  g_cij);
    float* v    = nullptr; cudaGetSymbolAddress((void**)&v,    g_v);
    int*   best = nullptr; cudaGetSymbolAddress((void**)&best, g_best);
    float* h1   = nullptr; cudaGetSymbolAddress((void**)&h1,   g_h1);
    float* h2   = nullptr; cudaGetSymbolAddress((void**)&h2,   g_h2);

    static bool attr_set = false;
    if (!attr_set) {
        cudaFuncSetAttribute(conv2_mma_kernel,
                             cudaFuncAttributeMaxDynamicSharedMemorySize, SMEM_CONV2);
        attr_set = true;
    }

    // 0) pre-split B + offset table
    bsplit_kernel<<<(N2 * K2 + 1023) / 1024, 1024>>>(pc_w, bpp);
    kofft_kernel<<<(K2 + 255) / 256, 256>>>(koff);
    // 1) conv1 + relu -> packed bf16 split
    conv1_kernel<<<dim3(BATCH, 8), 256>>>(image, conv_w, conv_b, x1p);
    // 2) im2col materialization
    im2col_kernel<<<M2, 256>>>(x1p, koff, aim);
    // 3) conv2: dense split-bf16 MMA GEMM, BK=32
    conv2_mma_kernel<<<dim3(N2 / 128, M2 / 128), 512, SMEM_CONV2>>>(aim, bpp, pc_b, c2);
    // 4) squash -> u
    squash_u_kernel<<<(BATCH * ROUTES + 255) / 256, 256>>>(c2, u);
    // 5) u_hat ([b][k][r][o]) — reuses big buffer
    uhat_kernel<<<dim3(ROUTES, BATCH / 32), 256>>>(W_obj, u, uhat);
    // 6) routing (3 iterations)
    zero_bij_kernel<<<(ROUTES * NCAPS + 255) / 256, 256>>>(bij);
    for (int it = 0; it < 3; it++) {
        softmax_routes_kernel<<<NCAPS, 256>>>(bij, cij);
        sv_kernel<<<dim3(BATCH, NCAPS), 128>>>(cij, uhat, v);
        if (it < 2)
            agree_kernel<<<dim3(NCAPS, ROUTES / 64), 256>>>(uhat, v, bij);
    }
    // 7) mask + obj output
    mask_kernel<<<2, 256>>>(v, out_obj, out_mask, best);
    // 8) decoder
    dec1_kernel<<<BATCH, 512>>>(v, best, dec_w1, dec_b1, h1);
    gemm_act_kernel<0><<<dim3(1024 / 64, BATCH / 64), 256>>>(h1, dec_w2, dec_b2, h2, BATCH, 1024, 512);
    gemm_act_kernel<1><<<dim3((784 + 63) / 64, BATCH / 64), 256>>>(h2, dec_w3, dec_b3, out_rec, BATCH, 784, 1024);
}

// round 15
// speedup vs baseline: 1.1844x; 1.0236x over previous
#include <cuda_runtime.h>
#include <cuda_bf16.h>
#include <stdint.h>
#include <math.h>

// ---------------- Problem constants ----------------
#define BATCH 512
#define C1 256
#define ROUTES 1152
#define NCAPS 10
#define CAPDIM 16
#define M2 (BATCH*36)     // 18432
#define K2 20736          // 256*81
#define N2 256
#define FLAT 9216

// ---------------- Device scratch ----------------
#define BIG_BYTES ((size_t)M2 * K2 * 4)
__device__ __align__(128) unsigned char g_big[BIG_BYTES];
__device__ __align__(16) uint32_t g_x1p[BATCH*C1*20*20];
__device__ __align__(16) uint32_t g_bp[(size_t)N2*K2];
__device__ __align__(16) int      g_kofft[K2];
__device__ __align__(16) float g_c2[BATCH*FLAT];
__device__ __align__(16) float g_u[BATCH*FLAT];
__device__ __align__(16) float g_bij[ROUTES*NCAPS];
__device__ __align__(16) float g_cij[ROUTES*NCAPS];
__device__ __align__(16) float g_v[BATCH*NCAPS*CAPDIM];
__device__ int   g_best[BATCH];
__device__ __align__(16) float g_h1[BATCH*512];
__device__ __align__(16) float g_h2[BATCH*1024];

// ---------------- pack helper ----------------
__device__ __forceinline__ uint32_t pack_split(float x) {
    __nv_bfloat16 h = __float2bfloat16(x);
    __nv_bfloat16 l = __float2bfloat16(x - __bfloat162float(h));
    return (uint32_t)__bfloat16_as_ushort(h) | ((uint32_t)__bfloat16_as_ushort(l) << 16);
}

__global__ void bsplit_kernel(const float* __restrict__ w, uint32_t* __restrict__ bp) {
    int i = blockIdx.x * 1024 + threadIdx.x;
    if (i < N2 * K2) bp[i] = pack_split(w[i]);
}

__global__ void kofft_kernel(int* __restrict__ tab) {
    int k = blockIdx.x * 256 + threadIdx.x;
    if (k >= K2) return;
    int ci = k / 81, rem = k - ci * 81;
    int ky = rem / 9, kx = rem - ky * 9;
    tab[k] = ci * 400 + ky * 20 + kx;
}

// ---------------- Conv1 -> packed split ----------------
__global__ void conv1_kernel(const float* __restrict__ img, const float* __restrict__ w,
                             const float* __restrict__ bias, uint32_t* __restrict__ x1p) {
    __shared__ float ism[784];
    __shared__ float wsm[32 * 81];
    int b = blockIdx.x, g = blockIdx.y;
    for (int i = threadIdx.x; i < 784; i += 256) ism[i] = img[b * 784 + i];
    for (int i = threadIdx.x; i < 2592; i += 256) wsm[i] = w[g * 2592 + i];
    __syncthreads();
    for (int idx = threadIdx.x; idx < 32 * 400; idx += 256) {
        int cl = idx / 400, pix = idx - cl * 400;
        int y = pix / 20, x = pix - y * 20;
        const float* wp = &wsm[cl * 81];
        float acc = bias[g * 32 + cl];
        #pragma unroll
        for (int ky = 0; ky < 9; ky++) {
            const float* irow = &ism[(y + ky) * 28 + x];
            #pragma unroll
            for (int kx = 0; kx < 9; kx++)
                acc += irow[kx] * wp[ky * 9 + kx];
        }
        x1p[(size_t)b * 102400 + (size_t)(g * 32 + cl) * 400 + pix] = pack_split(fmaxf(acc, 0.f));
    }
}

// ---------------- im2col: A[m][k] packed, uint4 stores ----------------
__global__ void im2col_kernel(const uint32_t* __restrict__ x1p, const int* __restrict__ kofft,
                              uint32_t* __restrict__ aim) {
    int m = blockIdx.x;
    int b = m / 36, s = m - b * 36;
    int oy = s / 6, ox = s - oy * 6;
    const uint32_t* base = x1p + (size_t)b * 102400 + oy * 40 + ox * 2;
    uint4* dst = reinterpret_cast<uint4*>(aim + (size_t)m * K2);
    const int4* kt = reinterpret_cast<const int4*>(kofft);
    for (int k4 = threadIdx.x; k4 < K2 / 4; k4 += 256) {
        int4 o = kt[k4];
        uint4 v;
        v.x = base[o.x]; v.y = base[o.y]; v.z = base[o.z]; v.w = base[o.w];
        dst[k4] = v;
    }
}

// ---------------- Conv2: split-bf16 MMA, BK=32, ldmatrix fragments ----------------
#define BK 32
#define RS 40   // smem row stride in bf16 elems (80B = 5x16B, conflict-free)
#define ARR_STG (128 * RS * 2)          // 10240 bytes per array per stage
#define SMEM_CONV2 (8 * ARR_STG)        // 81920

__device__ __forceinline__ void mma_bf16(float& c0, float& c1, float& c2, float& c3,
                                         uint32_t a0, uint32_t a1, uint32_t a2, uint32_t a3,
                                         uint32_t b0, uint32_t b1) {
    asm volatile(
        "mma.sync.aligned.m16n8k16.row.col.f32.bf16.bf16.f32 "
        "{%0,%1,%2,%3}, {%4,%5,%6,%7}, {%8,%9}, {%0,%1,%2,%3};\n"
        : "+f"(c0), "+f"(c1), "+f"(c2), "+f"(c3)
        : "r"(a0), "r"(a1), "r"(a2), "r"(a3), "r"(b0), "r"(b1));
}
__device__ __forceinline__ void ldm_x4(uint32_t a[4], uint32_t addr) {
    asm volatile("ldmatrix.sync.aligned.m8n8.x4.shared.b16 {%0,%1,%2,%3}, [%4];"
                 : "=r"(a[0]), "=r"(a[1]), "=r"(a[2]), "=r"(a[3]) : "r"(addr));
}
__device__ __forceinline__ void ldm_x2(uint32_t& b0, uint32_t& b1, uint32_t addr) {
    asm volatile("ldmatrix.sync.aligned.m8n8.x2.shared.b16 {%0,%1}, [%2];"
                 : "=r"(b0), "=r"(b1) : "r"(addr));
}

__global__ __launch_bounds__(512, 1)
void conv2_mma_kernel(const uint32_t* __restrict__ aim, const uint32_t* __restrict__ bp,
                      const float* __restrict__ bias, float* __restrict__ out) {
    extern __shared__ char smem[];
    uint32_t sb;
    asm("{ .reg .u64 t; cvta.to.shared.u64 t, %1; cvt.u32.u64 %0, t; }" : "=r"(sb) : "l"(smem));
    char* const pAH = smem;
    char* const pAL = smem + 2 * ARR_STG;
    char* const pBH = smem + 4 * ARR_STG;
    char* const pBL = smem + 6 * ARR_STG;

    const int t = threadIdx.x;
    const int m0 = blockIdx.y * 128;
    const int n0 = blockIdx.x * 128;

    // loader: row = t>>2 (0..127), k-eighth = (t&3)*8
    const int lr = t >> 2;
    const int kq = (t & 3) * 8;
    const uint32_t* abase = aim + (size_t)(m0 + lr) * K2 + kq;
    const uint32_t* bbase = bp + (size_t)(n0 + lr) * K2 + kq;
    const int sa = lr * RS + kq;

    // compute mapping: 16 warps = 4m x 4n, warp tile 32x32
    const int wid = t >> 5;
    const int wm = wid >> 2;
    const int wn = wid & 3;
    const int lane = t & 31;
    const int qr = lane >> 2;
    const int qc = (lane & 3) * 2;

    // ldmatrix lane-address components (bytes)
    const int aRow = (lane & 15);            // row within 16-row block
    const int aCol = (lane >> 4) << 4;       // 0 or 16 bytes (8 bf16)
    const int bRow = (lane & 7);
    const int bCol = ((lane >> 3) & 1) << 4; // 0 or 16 bytes

    float acc[2][4][4];
    #pragma unroll
    for (int i = 0; i < 2; i++)
        #pragma unroll
        for (int j = 0; j < 4; j++)
            #pragma unroll
            for (int r = 0; r < 4; r++) acc[i][j][r] = 0.f;

    uint4 ua0, ua1, ub0, ub1;

    #define STORE_STAGE(st) do { \
        uint4 h4, l4; \
        h4.x = __byte_perm(ua0.x, ua0.y, 0x5410); h4.y = __byte_perm(ua0.z, ua0.w, 0x5410); \
        h4.z = __byte_perm(ua1.x, ua1.y, 0x5410); h4.w = __byte_perm(ua1.z, ua1.w, 0x5410); \
        l4.x = __byte_perm(ua0.x, ua0.y, 0x7632); l4.y = __byte_perm(ua0.z, ua0.w, 0x7632); \
        l4.z = __byte_perm(ua1.x, ua1.y, 0x7632); l4.w = __byte_perm(ua1.z, ua1.w, 0x7632); \
        *reinterpret_cast<uint4*>(pAH + (st) * ARR_STG + sa * 2) = h4; \
        *reinterpret_cast<uint4*>(pAL + (st) * ARR_STG + sa * 2) = l4; \
        h4.x = __byte_perm(ub0.x, ub0.y, 0x5410); h4.y = __byte_perm(ub0.z, ub0.w, 0x5410); \
        h4.z = __byte_perm(ub1.x, ub1.y, 0x5410); h4.w = __byte_perm(ub1.z, ub1.w, 0x5410); \
        l4.x = __byte_perm(ub0.x, ub0.y, 0x7632); l4.y = __byte_perm(ub0.z, ub0.w, 0x7632); \
        l4.z = __byte_perm(ub1.x, ub1.y, 0x7632); l4.w = __byte_perm(ub1.z, ub1.w, 0x7632); \
        *reinterpret_cast<uint4*>(pBH + (st) * ARR_STG + sa * 2) = h4; \
        *reinterpret_cast<uint4*>(pBL + (st) * ARR_STG + sa * 2) = l4; \
    } while (0)

    // prologue: stage 0
    ua0 = *reinterpret_cast<const uint4*>(abase);
    ua1 = *reinterpret_cast<const uint4*>(abase + 4);
    ub0 = *reinterpret_cast<const uint4*>(bbase);
    ub1 = *reinterpret_cast<const uint4*>(bbase + 4);
    STORE_STAGE(0);
    __syncthreads();

    const int NSTEP = K2 / BK;   // 648
    for (int s = 0; s < NSTEP; s++) {
        const int cur = s & 1;
        const bool more = (s + 1 < NSTEP);
        if (more) {
            const uint32_t* ap = abase + (s + 1) * BK;
            const uint32_t* bpp2 = bbase + (s + 1) * BK;
            ua0 = *reinterpret_cast<const uint4*>(ap);
            ua1 = *reinterpret_cast<const uint4*>(ap + 4);
            ub0 = *reinterpret_cast<const uint4*>(bpp2);
            ub1 = *reinterpret_cast<const uint4*>(bpp2 + 4);
        }

        // compute: 2 k-steps of 16, fragments via ldmatrix
        {
            const uint32_t ahBase = sb + cur * ARR_STG;                 // AH
            const uint32_t alBase = sb + 2 * ARR_STG + cur * ARR_STG;   // AL
            const uint32_t bhBase = sb + 4 * ARR_STG + cur * ARR_STG;   // BH
            const uint32_t blBase = sb + 6 * ARR_STG + cur * ARR_STG;   // BL
            #pragma unroll
            for (int ks = 0; ks < 2; ks++) {
                const int kB = ks * 32;   // k-step byte offset (16 bf16)
                uint32_t ah[2][4], al[2][4], bh[4][2], bl[4][2];
                #pragma unroll
                for (int i = 0; i < 2; i++) {
                    uint32_t off = (uint32_t)(wm * 32 + i * 16 + aRow) * (RS * 2) + kB + aCol;
                    ldm_x4(ah[i], ahBase + off);
                    ldm_x4(al[i], alBase + off);
                }
                #pragma unroll
                for (int j = 0; j < 4; j++) {
                    uint32_t off = (uint32_t)(wn * 32 + j * 8 + bRow) * (RS * 2) + kB + bCol;
                    ldm_x2(bh[j][0], bh[j][1], bhBase + off);
                    ldm_x2(bl[j][0], bl[j][1], blBase + off);
                }
                #pragma unroll
                for (int i = 0; i < 2; i++)
                    #pragma unroll
                    for (int j = 0; j < 4; j++) {
                        mma_bf16(acc[i][j][0], acc[i][j][1], acc[i][j][2], acc[i][j][3],
                                 ah[i][0], ah[i][1], ah[i][2], ah[i][3], bh[j][0], bh[j][1]);
                        mma_bf16(acc[i][j][0], acc[i][j][1], acc[i][j][2], acc[i][j][3],
                                 ah[i][0], ah[i][1], ah[i][2], ah[i][3], bl[j][0], bl[j][1]);
                        mma_bf16(acc[i][j][0], acc[i][j][1], acc[i][j][2], acc[i][j][3],
                                 al[i][0], al[i][1], al[i][2], al[i][3], bh[j][0], bh[j][1]);
                    }
            }
        }

        if (more) STORE_STAGE(cur ^ 1);
        __syncthreads();
    }
    #undef STORE_STAGE

    // epilogue: C[m][n] -> out[b*FLAT + n*36 + s] + bias[n]
    #pragma unroll
    for (int i = 0; i < 2; i++) {
        #pragma unroll
        for (int j = 0; j < 4; j++) {
            int r = m0 + wm * 32 + i * 16 + qr;
            int c = n0 + wn * 32 + j * 8 + qc;
            #pragma unroll
            for (int rr = 0; rr < 2; rr++) {
                int m = r + rr * 8;
                int b = m / 36, sidx = m - b * 36;
                float* op = out + (size_t)b * FLAT + sidx;
                op[(c + 0) * 36] = acc[i][j][rr * 2 + 0] + bias[c + 0];
                op[(c + 1) * 36] = acc[i][j][rr * 2 + 1] + bias[c + 1];
            }
        }
    }
}

// ---------------- Squash u ----------------
__global__ void squash_u_kernel(const float* __restrict__ c2, float* __restrict__ u) {
    int i = blockIdx.x * 256 + threadIdx.x;
    if (i >= BATCH * ROUTES) return;
    const float4* p = reinterpret_cast<const float4*>(c2 + (size_t)i * 8);
    float4 a = p[0], b = p[1];
    float sn = a.x*a.x + a.y*a.y + a.z*a.z + a.w*a.w
             + b.x*b.x + b.y*b.y + b.z*b.z + b.w*b.w + 1e-7f;
    float sc = sqrtf(sn) / (1.f + sn);
    float4 oa = make_float4(a.x*sc, a.y*sc, a.z*sc, a.w*sc);
    float4 ob = make_float4(b.x*sc, b.y*sc, b.z*sc, b.w*sc);
    float4* q = reinterpret_cast<float4*>(u + (size_t)i * 8);
    q[0] = oa; q[1] = ob;
}

// ---------------- u_hat -> layout [b][k][r][o] ----------------
__global__ void uhat_kernel(const float* __restrict__ W, const float* __restrict__ u,
                            float* __restrict__ uhat) {
    __shared__ float Wsm[1280];
    __shared__ float usm[256];
    int r = blockIdx.x;
    int bg = blockIdx.y;
    for (int i = threadIdx.x; i < 1280; i += 256) Wsm[i] = W[(size_t)r * 1280 + i];
    {
        int i = threadIdx.x;
        int bb = bg * 32 + (i >> 3);
        usm[i] = u[(size_t)bb * FLAT + r * 8 + (i & 7)];
    }
    __syncthreads();
    for (int i = threadIdx.x; i < 5120; i += 256) {
        int bi = i / 160, ko = i - bi * 160;
        const float* wp = &Wsm[ko * 8];
        const float* up = &usm[bi * 8];
        float acc = 0.f;
        #pragma unroll
        for (int c = 0; c < 8; c++) acc += wp[c] * up[c];
        int k = ko >> 4, o = ko & 15;
        uhat[(((size_t)(bg * 32 + bi) * NCAPS + k) * ROUTES + r) * 16 + o] = acc;
    }
}

// ---------------- Routing ----------------
__global__ void zero_bij_kernel(float* __restrict__ bij) {
    int i = blockIdx.x * 256 + threadIdx.x;
    if (i < ROUTES * NCAPS) bij[i] = 0.f;
}

__global__ void softmax_routes_kernel(const float* __restrict__ b, float* __restrict__ c) {
    int k = blockIdx.x;
    __shared__ float red[256];
    int tid = threadIdx.x;
    float m = -1e30f;
    for (int r = tid; r < ROUTES; r += 256) m = fmaxf(m, b[r * 10 + k]);
    red[tid] = m; __syncthreads();
    for (int s = 128; s > 0; s >>= 1) {
        if (tid < s) red[tid] = fmaxf(red[tid], red[tid + s]);
        __syncthreads();
    }
    m = red[0]; __syncthreads();
    float sum = 0.f;
    for (int r = tid; r < ROUTES; r += 256) sum += expf(b[r * 10 + k] - m);
    red[tid] = sum; __syncthreads();
    for (int s = 128; s > 0; s >>= 1) {
        if (tid < s) red[tid] += red[tid + s];
        __syncthreads();
    }
    float inv = 1.f / red[0];
    for (int r = tid; r < ROUTES; r += 256) c[r * 10 + k] = expf(b[r * 10 + k] - m) * inv;
}

__global__ void sv_kernel(const float* __restrict__ cij, const float* __restrict__ uhat,
                          float* __restrict__ v) {
    int b = blockIdx.x, k = blockIdx.y;
    int tid = threadIdx.x;   // 128
    __shared__ float cs[ROUTES];
    __shared__ float4 red[128];
    for (int i = tid; i < ROUTES; i += 128) cs[i] = cij[i * 10 + k];
    __syncthreads();
    const float4* base = reinterpret_cast<const float4*>(
        uhat + ((size_t)(b * NCAPS + k)) * ROUTES * 16);
    int q = tid & 3, rr = tid >> 2;
    float4 acc = make_float4(0.f, 0.f, 0.f, 0.f);
    for (int r0 = 0; r0 < ROUTES; r0 += 32) {
        int r = r0 + rr;
        float c = cs[r];
        float4 x = base[r * 4 + q];
        acc.x += c * x.x; acc.y += c * x.y; acc.z += c * x.z; acc.w += c * x.w;
    }
    red[tid] = acc; __syncthreads();
    for (int s = 64; s >= 4; s >>= 1) {
        if (tid < s) {
            float4 o = red[tid + s];
            red[tid].x += o.x; red[tid].y += o.y; red[tid].z += o.z; red[tid].w += o.w;
        }
        __syncthreads();
    }
    if (tid == 0) {
        float sv16[16]; float sn = 0.f;
        #pragma unroll
        for (int q2 = 0; q2 < 4; q2++) {
            float4 x = red[q2];
            sv16[q2*4+0] = x.x; sv16[q2*4+1] = x.y; sv16[q2*4+2] = x.z; sv16[q2*4+3] = x.w;
            sn += x.x*x.x + x.y*x.y + x.z*x.z + x.w*x.w;
        }
        float sc = sqrtf(sn) / (1.f + sn);
        #pragma unroll
        for (int o = 0; o < 16; o++) v[(b * NCAPS + k) * 16 + o] = sv16[o] * sc;
    }
}

__global__ void agree_kernel(const float* __restrict__ uhat, const float* __restrict__ v,
                             float* __restrict__ bij) {
    int k = blockIdx.x;
    int r0 = blockIdx.y * 64;
    int tid = threadIdx.x;   // 256
    __shared__ __align__(16) float4 vs4[BATCH * 4];
    for (int i = tid; i < BATCH * 4; i += 256) {
        int b = i >> 2, q2 = i & 3;
        vs4[i] = *reinterpret_cast<const float4*>(v + (b * NCAPS + k) * 16 + q2 * 4);
    }
    __syncthreads();
    int q = tid & 3, rr = tid >> 2;
    int r = r0 + rr;
    const float4* U = reinterpret_cast<const float4*>(uhat);
    float acc = 0.f;
    for (int b = 0; b < BATCH; b++) {
        float4 x = U[((size_t)(b * NCAPS + k) * ROUTES + r) * 4 + q];
        float4 vv = vs4[b * 4 + q];
        acc += x.x*vv.x + x.y*vv.y + x.z*vv.z + x.w*vv.w;
    }
    acc += __shfl_down_sync(0xffffffffu, acc, 2);
    acc += __shfl_down_sync(0xffffffffu, acc, 1);
    if (q == 0) bij[r * 10 + k] += acc * (1.f / (float)BATCH);
}

// ---------------- Mask / argmax ----------------
__global__ void mask_kernel(const float* __restrict__ v, float* __restrict__ out_obj,
                            float* __restrict__ out_mask, int* __restrict__ best) {
    int b = blockIdx.x * blockDim.x + threadIdx.x;
    if (b >= BATCH) return;
    const float* vb = v + b * 160;
    float bestn = -1.f; int bi = 0;
    #pragma unroll
    for (int k = 0; k < 10; k++) {
        float sn = 0.f;
        #pragma unroll
        for (int o = 0; o < 16; o++) { float t = vb[k * 16 + o]; sn += t * t; }
        if (sn > bestn) { bestn = sn; bi = k; }
    }
    best[b] = bi;
    for (int i = 0; i < 160; i++) out_obj[b * 160 + i] = vb[i];
    #pragma unroll
    for (int k = 0; k < 10; k++) out_mask[b * 10 + k] = (k == bi) ? 1.f : 0.f;
}

// ---------------- Decoder ----------------
__global__ void dec1_kernel(const float* __restrict__ v, const int* __restrict__ best,
                            const float* __restrict__ w1, const float* __restrict__ b1,
                            float* __restrict__ h1) {
    int b = blockIdx.x;
    int j = threadIdx.x;
    __shared__ float vs[16];
    int bi = best[b];
    if (threadIdx.x < 16) vs[threadIdx.x] = v[b * 160 + bi * 16 + threadIdx.x];
    __syncthreads();
    float acc = b1[j];
    #pragma unroll
    for (int o = 0; o < 16; o++) acc += vs[o] * w1[(bi * 16 + o) * 512 + j];
    h1[b * 512 + j] = fmaxf(acc, 0.f);
}

template<int ACT>
__global__ void gemm_act_kernel(const float* __restrict__ A, const float* __restrict__ W,
                                const float* __restrict__ bias, float* __restrict__ C,
                                int M, int N, int K) {
    __shared__ float As[16][64];
    __shared__ float Bs[16][64];
    int tid = threadIdx.x;
    int m0 = blockIdx.y * 64, n0 = blockIdx.x * 64;
    int ty = tid >> 4, tx = tid & 15;
    float acc[4][4];
    #pragma unroll
    for (int i = 0; i < 4; i++)
        #pragma unroll
        for (int j = 0; j < 4; j++) acc[i][j] = 0.f;

    int lam = tid >> 2;
    int lak = (tid & 3) * 4;
    int lbk = tid >> 4;
    int lbn = (tid & 15) * 4;

    for (int k0 = 0; k0 < K; k0 += 16) {
        float4 av = *reinterpret_cast<const float4*>(A + (size_t)(m0 + lam) * K + k0 + lak);
        As[lak + 0][lam] = av.x; As[lak + 1][lam] = av.y;
        As[lak + 2][lam] = av.z; As[lak + 3][lam] = av.w;
        #pragma unroll
        for (int i = 0; i < 4; i++) {
            int n = n0 + lbn + i;
            Bs[lbk][lbn + i] = (n < N) ? W[(size_t)(k0 + lbk) * N + n] : 0.f;
        }
        __syncthreads();
        #pragma unroll
        for (int kk = 0; kk < 16; kk++) {
            float af[4], bf[4];
            #pragma unroll
            for (int i = 0; i < 4; i++) af[i] = As[kk][ty * 4 + i];
            #pragma unroll
            for (int j = 0; j < 4; j++) bf[j] = Bs[kk][tx * 4 + j];
            #pragma unroll
            for (int i = 0; i < 4; i++)
                #pragma unroll
                for (int j = 0; j < 4; j++)
                    acc[i][j] += af[i] * bf[j];
        }
        __syncthreads();
    }
    #pragma unroll
    for (int i = 0; i < 4; i++) {
        int m = m0 + ty * 4 + i;
        #pragma unroll
        for (int j = 0; j < 4; j++) {
            int n = n0 + tx * 4 + j;
            if (n < N) {
                float x = acc[i][j] + bias[n];
                if (ACT == 0) x = fmaxf(x, 0.f);
                else          x = 1.f / (1.f + expf(-x));
                C[(size_t)m * N + n] = x;
            }
        }
    }
}

// ---------------- Host launcher ----------------
extern "C" void kernel_launch(void* const* d_in, const int* in_sizes, int n_in,
                              void* d_out, int out_size) {
    const float* image  = (const float*)d_in[0];
    const float* conv_w = (const float*)d_in[1];
    const float* conv_b = (const float*)d_in[2];
    const float* pc_w   = (const float*)d_in[3];
    const float* pc_b   = (const float*)d_in[4];
    const float* W_obj  = (const float*)d_in[5];
    const float* dec_w1 = (const float*)d_in[6];
    const float* dec_b1 = (const float*)d_in[7];
    const float* dec_w2 = (const float*)d_in[8];
    const float* dec_b2 = (const float*)d_in[9];
    const float* dec_w3 = (const float*)d_in[10];
    const float* dec_b3 = (const float*)d_in[11];

    float* out = (float*)d_out;
    float* out_obj  = out;
    float* out_rec  = out + BATCH * 160;
    float* out_mask = out + BATCH * (160 + 784);

    unsigned char* big = nullptr; cudaGetSymbolAddress((void**)&big, g_big);
    uint32_t* aim  = (uint32_t*)big;     // live: im2col -> conv2
    float*    uhat = (float*)big;        // live after conv2
    uint32_t* x1p  = nullptr; cudaGetSymbolAddress((void**)&x1p,  g_x1p);
    uint32_t* bpp  = nullptr; cudaGetSymbolAddress((void**)&bpp,  g_bp);
    int*      koff = nullptr; cudaGetSymbolAddress((void**)&koff, g_kofft);
    float* c2   = nullptr; cudaGetSymbolAddress((void**)&c2,   g_c2);
    float* u    = nullptr; cudaGetSymbolAddress((void**)&u,    g_u);
    float* bij  = nullptr; cudaGetSymbolAddress((void**)&bij,  g_bij);
    float* cij  = nullptr; cudaGetSymbolAddress((void**)&cij,  g_cij);
    float* v    = nullptr; cudaGetSymbolAddress((void**)&v,    g_v);
    int*   best = nullptr; cudaGetSymbolAddress((void**)&best, g_best);
    float* h1   = nullptr; cudaGetSymbolAddress((void**)&h1,   g_h1);
    float* h2   = nullptr; cudaGetSymbolAddress((void**)&h2,   g_h2);

    static bool attr_set = false;
    if (!attr_set) {
        cudaFuncSetAttribute(conv2_mma_kernel,
                             cudaFuncAttributeMaxDynamicSharedMemorySize, SMEM_CONV2);
        attr_set = true;
    }

    // 0) pre-split B + offset table
    bsplit_kernel<<<(N2 * K2 + 1023) / 1024, 1024>>>(pc_w, bpp);
    kofft_kernel<<<(K2 + 255) / 256, 256>>>(koff);
    // 1) conv1 + relu -> packed bf16 split
    conv1_kernel<<<dim3(BATCH, 8), 256>>>(image, conv_w, conv_b, x1p);
    // 2) im2col materialization (uint4 stores)
    im2col_kernel<<<M2, 256>>>(x1p, koff, aim);
    // 3) conv2: split-bf16 MMA GEMM, BK=32, ldmatrix
    conv2_mma_kernel<<<dim3(N2 / 128, M2 / 128), 512, SMEM_CONV2>>>(aim, bpp, pc_b, c2);
    // 4) squash -> u
    squash_u_kernel<<<(BATCH * ROUTES + 255) / 256, 256>>>(c2, u);
    // 5) u_hat ([b][k][r][o]) — reuses big buffer
    uhat_kernel<<<dim3(ROUTES, BATCH / 32), 256>>>(W_obj, u, uhat);
    // 6) routing (3 iterations)
    zero_bij_kernel<<<(ROUTES * NCAPS + 255) / 256, 256>>>(bij);
    for (int it = 0; it < 3; it++) {
        softmax_routes_kernel<<<NCAPS, 256>>>(bij, cij);
        sv_kernel<<<dim3(BATCH, NCAPS), 128>>>(cij, uhat, v);
        if (it < 2)
            agree_kernel<<<dim3(NCAPS, ROUTES / 64), 256>>>(uhat, v, bij);
    }
    // 7) mask + obj output
    mask_kernel<<<2, 256>>>(v, out_obj, out_mask, best);
    // 8) decoder
    dec1_kernel<<<BATCH, 512>>>(v, best, dec_w1, dec_b1, h1);
    gemm_act_kernel<0><<<dim3(1024 / 64, BATCH / 64), 256>>>(h1, dec_w2, dec_b2, h2, BATCH, 1024, 512);
    gemm_act_kernel<1><<<dim3((784 + 63) / 64, BATCH / 64), 256>>>(h2, dec_w3, dec_b3, out_rec, BATCH, 784, 1024);
}

// round 16
// speedup vs baseline: 1.3876x; 1.1716x over previous
#include <cuda_runtime.h>
#include <cuda_bf16.h>
#include <stdint.h>
#include <math.h>

// ---------------- Problem constants ----------------
#define BATCH 512
#define C1 256
#define ROUTES 1152
#define NCAPS 10
#define CAPDIM 16
#define M2 (BATCH*36)     // 18432
#define K2 20736          // 256*81
#define N2 256
#define FLAT 9216

// ---------------- Device scratch ----------------
#define BIG_BYTES ((size_t)M2 * K2 * 4)
__device__ __align__(128) unsigned char g_big[BIG_BYTES];
__device__ __align__(16) uint32_t g_x1p[BATCH*C1*20*20];
__device__ __align__(16) uint32_t g_bp[(size_t)N2*K2];
__device__ __align__(16) int      g_kofft[K2];
__device__ __align__(16) float g_c2[BATCH*FLAT];
__device__ __align__(16) float g_u[BATCH*FLAT];
__device__ __align__(16) float g_bij[ROUTES*NCAPS];
__device__ __align__(16) float g_cij[ROUTES*NCAPS];
__device__ __align__(16) float g_v[BATCH*NCAPS*CAPDIM];
__device__ int   g_best[BATCH];
__device__ __align__(16) float g_h1[BATCH*512];
__device__ __align__(16) float g_h2[BATCH*1024];

// ---------------- pack helper ----------------
__device__ __forceinline__ uint32_t pack_split(float x) {
    __nv_bfloat16 h = __float2bfloat16(x);
    __nv_bfloat16 l = __float2bfloat16(x - __bfloat162float(h));
    return (uint32_t)__bfloat16_as_ushort(h) | ((uint32_t)__bfloat16_as_ushort(l) << 16);
}

__global__ void bsplit_kernel(const float* __restrict__ w, uint32_t* __restrict__ bp) {
    int i = blockIdx.x * 1024 + threadIdx.x;
    if (i < N2 * K2) bp[i] = pack_split(w[i]);
}

__global__ void kofft_kernel(int* __restrict__ tab) {
    int k = blockIdx.x * 256 + threadIdx.x;
    if (k >= K2) return;
    int ci = k / 81, rem = k - ci * 81;
    int ky = rem / 9, kx = rem - ky * 9;
    tab[k] = ci * 400 + ky * 20 + kx;
}

// ---------------- Conv1: register-tiled 5px per thread ----------------
__global__ void conv1_kernel(const float* __restrict__ img, const float* __restrict__ w,
                             const float* __restrict__ bias, uint32_t* __restrict__ x1p) {
    __shared__ float ism[784];
    __shared__ float wsm[32 * 81];
    int b = blockIdx.x, g = blockIdx.y;
    for (int i = threadIdx.x; i < 784; i += 256) ism[i] = img[b * 784 + i];
    for (int i = threadIdx.x; i < 2592; i += 256) wsm[i] = w[g * 2592 + i];
    __syncthreads();
    // 32 ch x 80 groups (20 y x 4 xg of 5 px) = 2560 items / 256 threads = 10 each
    for (int it = 0; it < 10; it++) {
        int idx = it * 256 + threadIdx.x;      // 0..2559
        int cl = idx >> 6 >> 1;                // idx / 128? no -- compute directly:
        cl = idx / 80;
        int g5 = idx - cl * 80;                // 0..79
        int y = g5 >> 2;                       // 0..19
        int x0 = (g5 & 3) * 5;                 // 0,5,10,15
        const float* wp = &wsm[cl * 81];
        float bv = bias[g * 32 + cl];
        float acc[5];
        #pragma unroll
        for (int p = 0; p < 5; p++) acc[p] = bv;
        #pragma unroll
        for (int ky = 0; ky < 9; ky++) {
            const float* irow = &ism[(y + ky) * 28 + x0];
            float r[13];
            #pragma unroll
            for (int i = 0; i < 13; i++) r[i] = irow[i];
            #pragma unroll
            for (int kx = 0; kx < 9; kx++) {
                float wv = wp[ky * 9 + kx];
                #pragma unroll
                for (int p = 0; p < 5; p++) acc[p] += r[kx + p] * wv;
            }
        }
        uint32_t* op = x1p + (size_t)b * 102400 + (size_t)(g * 32 + cl) * 400 + y * 20 + x0;
        #pragma unroll
        for (int p = 0; p < 5; p++) op[p] = pack_split(fmaxf(acc[p], 0.f));
    }
}

// ---------------- im2col: A[m][k] packed, uint4 stores ----------------
__global__ void im2col_kernel(const uint32_t* __restrict__ x1p, const int* __restrict__ kofft,
                              uint32_t* __restrict__ aim) {
    int m = blockIdx.x;
    int b = m / 36, s = m - b * 36;
    int oy = s / 6, ox = s - oy * 6;
    const uint32_t* base = x1p + (size_t)b * 102400 + oy * 40 + ox * 2;
    uint4* dst = reinterpret_cast<uint4*>(aim + (size_t)m * K2);
    const int4* kt = reinterpret_cast<const int4*>(kofft);
    for (int k4 = threadIdx.x; k4 < K2 / 4; k4 += 256) {
        int4 o = kt[k4];
        uint4 v;
        v.x = base[o.x]; v.y = base[o.y]; v.z = base[o.z]; v.w = base[o.w];
        dst[k4] = v;
    }
}

// ---------------- Conv2: split-bf16 MMA, BK=32, ldmatrix fragments ----------------
#define BK 32
#define RS 40
#define ARR_STG (128 * RS * 2)
#define SMEM_CONV2 (8 * ARR_STG)

__device__ __forceinline__ void mma_bf16(float& c0, float& c1, float& c2, float& c3,
                                         uint32_t a0, uint32_t a1, uint32_t a2, uint32_t a3,
                                         uint32_t b0, uint32_t b1) {
    asm volatile(
        "mma.sync.aligned.m16n8k16.row.col.f32.bf16.bf16.f32 "
        "{%0,%1,%2,%3}, {%4,%5,%6,%7}, {%8,%9}, {%0,%1,%2,%3};\n"
        : "+f"(c0), "+f"(c1), "+f"(c2), "+f"(c3)
        : "r"(a0), "r"(a1), "r"(a2), "r"(a3), "r"(b0), "r"(b1));
}
__device__ __forceinline__ void ldm_x4(uint32_t a[4], uint32_t addr) {
    asm volatile("ldmatrix.sync.aligned.m8n8.x4.shared.b16 {%0,%1,%2,%3}, [%4];"
                 : "=r"(a[0]), "=r"(a[1]), "=r"(a[2]), "=r"(a[3]) : "r"(addr));
}
__device__ __forceinline__ void ldm_x2(uint32_t& b0, uint32_t& b1, uint32_t addr) {
    asm volatile("ldmatrix.sync.aligned.m8n8.x2.shared.b16 {%0,%1}, [%2];"
                 : "=r"(b0), "=r"(b1) : "r"(addr));
}

__global__ __launch_bounds__(512, 1)
void conv2_mma_kernel(const uint32_t* __restrict__ aim, const uint32_t* __restrict__ bp,
                      const float* __restrict__ bias, float* __restrict__ out) {
    extern __shared__ char smem[];
    uint32_t sb;
    asm("{ .reg .u64 t; cvta.to.shared.u64 t, %1; cvt.u32.u64 %0, t; }" : "=r"(sb) : "l"(smem));
    char* const pAH = smem;
    char* const pAL = smem + 2 * ARR_STG;
    char* const pBH = smem + 4 * ARR_STG;
    char* const pBL = smem + 6 * ARR_STG;

    const int t = threadIdx.x;
    const int m0 = blockIdx.y * 128;
    const int n0 = blockIdx.x * 128;

    const int lr = t >> 2;
    const int kq = (t & 3) * 8;
    const uint32_t* abase = aim + (size_t)(m0 + lr) * K2 + kq;
    const uint32_t* bbase = bp + (size_t)(n0 + lr) * K2 + kq;
    const int sa = lr * RS + kq;

    const int wid = t >> 5;
    const int wm = wid >> 2;
    const int wn = wid & 3;
    const int lane = t & 31;
    const int qr = lane >> 2;
    const int qc = (lane & 3) * 2;

    const int aRow = (lane & 15);
    const int aCol = (lane >> 4) << 4;
    const int bRow = (lane & 7);
    const int bCol = ((lane >> 3) & 1) << 4;

    float acc[2][4][4];
    #pragma unroll
    for (int i = 0; i < 2; i++)
        #pragma unroll
        for (int j = 0; j < 4; j++)
            #pragma unroll
            for (int r = 0; r < 4; r++) acc[i][j][r] = 0.f;

    uint4 ua0, ua1, ub0, ub1;

    #define STORE_STAGE(st) do { \
        uint4 h4, l4; \
        h4.x = __byte_perm(ua0.x, ua0.y, 0x5410); h4.y = __byte_perm(ua0.z, ua0.w, 0x5410); \
        h4.z = __byte_perm(ua1.x, ua1.y, 0x5410); h4.w = __byte_perm(ua1.z, ua1.w, 0x5410); \
        l4.x = __byte_perm(ua0.x, ua0.y, 0x7632); l4.y = __byte_perm(ua0.z, ua0.w, 0x7632); \
        l4.z = __byte_perm(ua1.x, ua1.y, 0x7632); l4.w = __byte_perm(ua1.z, ua1.w, 0x7632); \
        *reinterpret_cast<uint4*>(pAH + (st) * ARR_STG + sa * 2) = h4; \
        *reinterpret_cast<uint4*>(pAL + (st) * ARR_STG + sa * 2) = l4; \
        h4.x = __byte_perm(ub0.x, ub0.y, 0x5410); h4.y = __byte_perm(ub0.z, ub0.w, 0x5410); \
        h4.z = __byte_perm(ub1.x, ub1.y, 0x5410); h4.w = __byte_perm(ub1.z, ub1.w, 0x5410); \
        l4.x = __byte_perm(ub0.x, ub0.y, 0x7632); l4.y = __byte_perm(ub0.z, ub0.w, 0x7632); \
        l4.z = __byte_perm(ub1.x, ub1.y, 0x7632); l4.w = __byte_perm(ub1.z, ub1.w, 0x7632); \
        *reinterpret_cast<uint4*>(pBH + (st) * ARR_STG + sa * 2) = h4; \
        *reinterpret_cast<uint4*>(pBL + (st) * ARR_STG + sa * 2) = l4; \
    } while (0)

    ua0 = *reinterpret_cast<const uint4*>(abase);
    ua1 = *reinterpret_cast<const uint4*>(abase + 4);
    ub0 = *reinterpret_cast<const uint4*>(bbase);
    ub1 = *reinterpret_cast<const uint4*>(bbase + 4);
    STORE_STAGE(0);
    __syncthreads();

    const int NSTEP = K2 / BK;   // 648
    for (int s = 0; s < NSTEP; s++) {
        const int cur = s & 1;
        const bool more = (s + 1 < NSTEP);
        if (more) {
            const uint32_t* ap = abase + (s + 1) * BK;
            const uint32_t* bpp2 = bbase + (s + 1) * BK;
            ua0 = *reinterpret_cast<const uint4*>(ap);
            ua1 = *reinterpret_cast<const uint4*>(ap + 4);
            ub0 = *reinterpret_cast<const uint4*>(bpp2);
            ub1 = *reinterpret_cast<const uint4*>(bpp2 + 4);
        }

        {
            const uint32_t ahBase = sb + cur * ARR_STG;
            const uint32_t alBase = sb + 2 * ARR_STG + cur * ARR_STG;
            const uint32_t bhBase = sb + 4 * ARR_STG + cur * ARR_STG;
            const uint32_t blBase = sb + 6 * ARR_STG + cur * ARR_STG;
            #pragma unroll
            for (int ks = 0; ks < 2; ks++) {
                const int kB = ks * 32;
                uint32_t ah[2][4], al[2][4], bh[4][2], bl[4][2];
                #pragma unroll
                for (int i = 0; i < 2; i++) {
                    uint32_t off = (uint32_t)(wm * 32 + i * 16 + aRow) * (RS * 2) + kB + aCol;
                    ldm_x4(ah[i], ahBase + off);
                    ldm_x4(al[i], alBase + off);
                }
                #pragma unroll
                for (int j = 0; j < 4; j++) {
                    uint32_t off = (uint32_t)(wn * 32 + j * 8 + bRow) * (RS * 2) + kB + bCol;
                    ldm_x2(bh[j][0], bh[j][1], bhBase + off);
                    ldm_x2(bl[j][0], bl[j][1], blBase + off);
                }
                #pragma unroll
                for (int i = 0; i < 2; i++)
                    #pragma unroll
                    for (int j = 0; j < 4; j++) {
                        mma_bf16(acc[i][j][0], acc[i][j][1], acc[i][j][2], acc[i][j][3],
                                 ah[i][0], ah[i][1], ah[i][2], ah[i][3], bh[j][0], bh[j][1]);
                        mma_bf16(acc[i][j][0], acc[i][j][1], acc[i][j][2], acc[i][j][3],
                                 ah[i][0], ah[i][1], ah[i][2], ah[i][3], bl[j][0], bl[j][1]);
                        mma_bf16(acc[i][j][0], acc[i][j][1], acc[i][j][2], acc[i][j][3],
                                 al[i][0], al[i][1], al[i][2], al[i][3], bh[j][0], bh[j][1]);
                    }
            }
        }

        if (more) STORE_STAGE(cur ^ 1);
        __syncthreads();
    }
    #undef STORE_STAGE

    #pragma unroll
    for (int i = 0; i < 2; i++) {
        #pragma unroll
        for (int j = 0; j < 4; j++) {
            int r = m0 + wm * 32 + i * 16 + qr;
            int c = n0 + wn * 32 + j * 8 + qc;
            #pragma unroll
            for (int rr = 0; rr < 2; rr++) {
                int m = r + rr * 8;
                int b = m / 36, sidx = m - b * 36;
                float* op = out + (size_t)b * FLAT + sidx;
                op[(c + 0) * 36] = acc[i][j][rr * 2 + 0] + bias[c + 0];
                op[(c + 1) * 36] = acc[i][j][rr * 2 + 1] + bias[c + 1];
            }
        }
    }
}

// ---------------- Squash u ----------------
__global__ void squash_u_kernel(const float* __restrict__ c2, float* __restrict__ u) {
    int i = blockIdx.x * 256 + threadIdx.x;
    if (i >= BATCH * ROUTES) return;
    const float4* p = reinterpret_cast<const float4*>(c2 + (size_t)i * 8);
    float4 a = p[0], b = p[1];
    float sn = a.x*a.x + a.y*a.y + a.z*a.z + a.w*a.w
             + b.x*b.x + b.y*b.y + b.z*b.z + b.w*b.w + 1e-7f;
    float sc = sqrtf(sn) / (1.f + sn);
    float4 oa = make_float4(a.x*sc, a.y*sc, a.z*sc, a.w*sc);
    float4 ob = make_float4(b.x*sc, b.y*sc, b.z*sc, b.w*sc);
    float4* q = reinterpret_cast<float4*>(u + (size_t)i * 8);
    q[0] = oa; q[1] = ob;
}

// ---------------- u_hat: vectorized, layout [b][k][r][o] ----------------
__global__ void uhat_kernel(const float* __restrict__ W, const float* __restrict__ u,
                            float* __restrict__ uhat) {
    __shared__ __align__(16) float Wsm[1280];
    __shared__ float usm[256];
    int r = blockIdx.x;
    int bg = blockIdx.y;
    {
        // load 1280 floats = 320 float4
        const float4* Wg = reinterpret_cast<const float4*>(W + (size_t)r * 1280);
        float4* Ws4 = reinterpret_cast<float4*>(Wsm);
        for (int i = threadIdx.x; i < 320; i += 256) Ws4[i] = Wg[i];
    }
    {
        int i = threadIdx.x;
        int bb = bg * 32 + (i >> 3);
        usm[i] = u[(size_t)bb * FLAT + r * 8 + (i & 7)];
    }
    __syncthreads();
    const int bi = threadIdx.x >> 3;          // 0..31
    const int part = threadIdx.x & 7;         // 0..7
    float u8[8];
    #pragma unroll
    for (int c = 0; c < 8; c++) u8[c] = usm[bi * 8 + c];
    const int bb = bg * 32 + bi;
    #pragma unroll
    for (int q = 0; q < 5; q++) {
        int f4o = part + q * 8;               // 0..39, covers ko = f4o*4..+3
        float res[4];
        #pragma unroll
        for (int e = 0; e < 4; e++) {
            const float* wp = &Wsm[(f4o * 4 + e) * 8];
            float a = 0.f;
            #pragma unroll
            for (int c = 0; c < 8; c++) a += wp[c] * u8[c];
            res[e] = a;
        }
        int ko = f4o * 4;
        int k = ko >> 4, o = ko & 15;
        float* dst = uhat + (((size_t)bb * NCAPS + k) * ROUTES + r) * 16 + o;
        *reinterpret_cast<float4*>(dst) = make_float4(res[0], res[1], res[2], res[3]);
    }
}

// ---------------- Routing ----------------
__global__ void zero_bij_kernel(float* __restrict__ bij) {
    int i = blockIdx.x * 256 + threadIdx.x;
    if (i < ROUTES * NCAPS) bij[i] = 0.f;
}

__global__ void softmax_routes_kernel(const float* __restrict__ b, float* __restrict__ c) {
    int k = blockIdx.x;
    __shared__ float red[256];
    int tid = threadIdx.x;
    float m = -1e30f;
    for (int r = tid; r < ROUTES; r += 256) m = fmaxf(m, b[r * 10 + k]);
    red[tid] = m; __syncthreads();
    for (int s = 128; s > 0; s >>= 1) {
        if (tid < s) red[tid] = fmaxf(red[tid], red[tid + s]);
        __syncthreads();
    }
    m = red[0]; __syncthreads();
    float sum = 0.f;
    for (int r = tid; r < ROUTES; r += 256) sum += expf(b[r * 10 + k] - m);
    red[tid] = sum; __syncthreads();
    for (int s = 128; s > 0; s >>= 1) {
        if (tid < s) red[tid] += red[tid + s];
        __syncthreads();
    }
    float inv = 1.f / red[0];
    for (int r = tid; r < ROUTES; r += 256) c[r * 10 + k] = expf(b[r * 10 + k] - m) * inv;
}

__global__ void sv_kernel(const float* __restrict__ cij, const float* __restrict__ uhat,
                          float* __restrict__ v) {
    int b = blockIdx.x, k = blockIdx.y;
    int tid = threadIdx.x;   // 128
    __shared__ float cs[ROUTES];
    __shared__ float4 red[128];
    for (int i = tid; i < ROUTES; i += 128) cs[i] = cij[i * 10 + k];
    __syncthreads();
    const float4* base = reinterpret_cast<const float4*>(
        uhat + ((size_t)(b * NCAPS + k)) * ROUTES * 16);
    int q = tid & 3, rr = tid >> 2;
    float4 acc = make_float4(0.f, 0.f, 0.f, 0.f);
    for (int r0 = 0; r0 < ROUTES; r0 += 32) {
        int r = r0 + rr;
        float c = cs[r];
        float4 x = base[r * 4 + q];
        acc.x += c * x.x; acc.y += c * x.y; acc.z += c * x.z; acc.w += c * x.w;
    }
    red[tid] = acc; __syncthreads();
    for (int s = 64; s >= 4; s >>= 1) {
        if (tid < s) {
            float4 o = red[tid + s];
            red[tid].x += o.x; red[tid].y += o.y; red[tid].z += o.z; red[tid].w += o.w;
        }
        __syncthreads();
    }
    if (tid == 0) {
        float sv16[16]; float sn = 0.f;
        #pragma unroll
        for (int q2 = 0; q2 < 4; q2++) {
            float4 x = red[q2];
            sv16[q2*4+0] = x.x; sv16[q2*4+1] = x.y; sv16[q2*4+2] = x.z; sv16[q2*4+3] = x.w;
            sn += x.x*x.x + x.y*x.y + x.z*x.z + x.w*x.w;
        }
        float sc = sqrtf(sn) / (1.f + sn);
        #pragma unroll
        for (int o = 0; o < 16; o++) v[(b * NCAPS + k) * 16 + o] = sv16[o] * sc;
    }
}

__global__ void agree_kernel(const float* __restrict__ uhat, const float* __restrict__ v,
                             float* __restrict__ bij) {
    int k = blockIdx.x;
    int r0 = blockIdx.y * 64;
    int tid = threadIdx.x;   // 256
    __shared__ __align__(16) float4 vs4[BATCH * 4];
    for (int i = tid; i < BATCH * 4; i += 256) {
        int b = i >> 2, q2 = i & 3;
        vs4[i] = *reinterpret_cast<const float4*>(v + (b * NCAPS + k) * 16 + q2 * 4);
    }
    __syncthreads();
    int q = tid & 3, rr = tid >> 2;
    int r = r0 + rr;
    const float4* U = reinterpret_cast<const float4*>(uhat);
    float acc = 0.f;
    for (int b = 0; b < BATCH; b++) {
        float4 x = U[((size_t)(b * NCAPS + k) * ROUTES + r) * 4 + q];
        float4 vv = vs4[b * 4 + q];
        acc += x.x*vv.x + x.y*vv.y + x.z*vv.z + x.w*vv.w;
    }
    acc += __shfl_down_sync(0xffffffffu, acc, 2);
    acc += __shfl_down_sync(0xffffffffu, acc, 1);
    if (q == 0) bij[r * 10 + k] += acc * (1.f / (float)BATCH);
}

// ---------------- Mask / argmax ----------------
__global__ void mask_kernel(const float* __restrict__ v, float* __restrict__ out_obj,
                            float* __restrict__ out_mask, int* __restrict__ best) {
    int b = blockIdx.x * blockDim.x + threadIdx.x;
    if (b >= BATCH) return;
    const float* vb = v + b * 160;
    float bestn = -1.f; int bi = 0;
    #pragma unroll
    for (int k = 0; k < 10; k++) {
        float sn = 0.f;
        #pragma unroll
        for (int o = 0; o < 16; o++) { float t = vb[k * 16 + o]; sn += t * t; }
        if (sn > bestn) { bestn = sn; bi = k; }
    }
    best[b] = bi;
    for (int i = 0; i < 160; i++) out_obj[b * 160 + i] = vb[i];
    #pragma unroll
    for (int k = 0; k < 10; k++) out_mask[b * 10 + k] = (k == bi) ? 1.f : 0.f;
}

// ---------------- Decoder ----------------
__global__ void dec1_kernel(const float* __restrict__ v, const int* __restrict__ best,
                            const float* __restrict__ w1, const float* __restrict__ b1,
                            float* __restrict__ h1) {
    int b = blockIdx.x;
    int j = threadIdx.x;
    __shared__ float vs[16];
    int bi = best[b];
    if (threadIdx.x < 16) vs[threadIdx.x] = v[b * 160 + bi * 16 + threadIdx.x];
    __syncthreads();
    float acc = b1[j];
    #pragma unroll
    for (int o = 0; o < 16; o++) acc += vs[o] * w1[(bi * 16 + o) * 512 + j];
    h1[b * 512 + j] = fmaxf(acc, 0.f);
}

template<int ACT>
__global__ void gemm_act_kernel(const float* __restrict__ A, const float* __restrict__ W,
                                const float* __restrict__ bias, float* __restrict__ C,
                                int M, int N, int K) {
    __shared__ float As[16][64];
    __shared__ float Bs[16][64];
    int tid = threadIdx.x;
    int m0 = blockIdx.y * 64, n0 = blockIdx.x * 64;
    int ty = tid >> 4, tx = tid & 15;
    float acc[4][4];
    #pragma unroll
    for (int i = 0; i < 4; i++)
        #pragma unroll
        for (int j = 0; j < 4; j++) acc[i][j] = 0.f;

    int lam = tid >> 2;
    int lak = (tid & 3) * 4;
    int lbk = tid >> 4;
    int lbn = (tid & 15) * 4;

    for (int k0 = 0; k0 < K; k0 += 16) {
        float4 av = *reinterpret_cast<const float4*>(A + (size_t)(m0 + lam) * K + k0 + lak);
        As[lak + 0][lam] = av.x; As[lak + 1][lam] = av.y;
        As[lak + 2][lam] = av.z; As[lak + 3][lam] = av.w;
        #pragma unroll
        for (int i = 0; i < 4; i++) {
            int n = n0 + lbn + i;
            Bs[lbk][lbn + i] = (n < N) ? W[(size_t)(k0 + lbk) * N + n] : 0.f;
        }
        __syncthreads();
        #pragma unroll
        for (int kk = 0; kk < 16; kk++) {
            float af[4], bf[4];
            #pragma unroll
            for (int i = 0; i < 4; i++) af[i] = As[kk][ty * 4 + i];
            #pragma unroll
            for (int j = 0; j < 4; j++) bf[j] = Bs[kk][tx * 4 + j];
            #pragma unroll
            for (int i = 0; i < 4; i++)
                #pragma unroll
                for (int j = 0; j < 4; j++)
                    acc[i][j] += af[i] * bf[j];
        }
        __syncthreads();
    }
    #pragma unroll
    for (int i = 0; i < 4; i++) {
        int m = m0 + ty * 4 + i;
        #pragma unroll
        for (int j = 0; j < 4; j++) {
            int n = n0 + tx * 4 + j;
            if (n < N) {
                float x = acc[i][j] + bias[n];
                if (ACT == 0) x = fmaxf(x, 0.f);
                else          x = 1.f / (1.f + expf(-x));
                C[(size_t)m * N + n] = x;
            }
        }
    }
}

// ---------------- Host launcher ----------------
extern "C" void kernel_launch(void* const* d_in, const int* in_sizes, int n_in,
                              void* d_out, int out_size) {
    const float* image  = (const float*)d_in[0];
    const float* conv_w = (const float*)d_in[1];
    const float* conv_b = (const float*)d_in[2];
    const float* pc_w   = (const float*)d_in[3];
    const float* pc_b   = (const float*)d_in[4];
    const float* W_obj  = (const float*)d_in[5];
    const float* dec_w1 = (const float*)d_in[6];
    const float* dec_b1 = (const float*)d_in[7];
    const float* dec_w2 = (const float*)d_in[8];
    const float* dec_b2 = (const float*)d_in[9];
    const float* dec_w3 = (const float*)d_in[10];
    const float* dec_b3 = (const float*)d_in[11];

    float* out = (float*)d_out;
    float* out_obj  = out;
    float* out_rec  = out + BATCH * 160;
    float* out_mask = out + BATCH * (160 + 784);

    unsigned char* big = nullptr; cudaGetSymbolAddress((void**)&big, g_big);
    uint32_t* aim  = (uint32_t*)big;
    float*    uhat = (float*)big;
    uint32_t* x1p  = nullptr; cudaGetSymbolAddress((void**)&x1p,  g_x1p);
    uint32_t* bpp  = nullptr; cudaGetSymbolAddress((void**)&bpp,  g_bp);
    int*      koff = nullptr; cudaGetSymbolAddress((void**)&koff, g_kofft);
    float* c2   = nullptr; cudaGetSymbolAddress((void**)&c2,   g_c2);
    float* u    = nullptr; cudaGetSymbolAddress((void**)&u,    g_u);
    float* bij  = nullptr; cudaGetSymbolAddress((void**)&bij,  g_bij);
    float* cij  = nullptr; cudaGetSymbolAddress((void**)&cij,  g_cij);
    float* v    = nullptr; cudaGetSymbolAddress((void**)&v,    g_v);
    int*   best = nullptr; cudaGetSymbolAddress((void**)&best, g_best);
    float* h1   = nullptr; cudaGetSymbolAddress((void**)&h1,   g_h1);
    float* h2   = nullptr; cudaGetSymbolAddress((void**)&h2,   g_h2);

    static bool attr_set = false;
    if (!attr_set) {
        cudaFuncSetAttribute(conv2_mma_kernel,
                             cudaFuncAttributeMaxDynamicSharedMemorySize, SMEM_CONV2);
        attr_set = true;
    }

    // 0) pre-split B + offset table
    bsplit_kernel<<<(N2 * K2 + 1023) / 1024, 1024>>>(pc_w, bpp);
    kofft_kernel<<<(K2 + 255) / 256, 256>>>(koff);
    // 1) conv1 + relu -> packed bf16 split (register-tiled)
    conv1_kernel<<<dim3(BATCH, 8), 256>>>(image, conv_w, conv_b, x1p);
    // 2) im2col materialization
    im2col_kernel<<<M2, 256>>>(x1p, koff, aim);
    // 3) conv2: split-bf16 MMA GEMM, BK=32, ldmatrix
    conv2_mma_kernel<<<dim3(N2 / 128, M2 / 128), 512, SMEM_CONV2>>>(aim, bpp, pc_b, c2);
    // 4) squash -> u
    squash_u_kernel<<<(BATCH * ROUTES + 255) / 256, 256>>>(c2, u);
    // 5) u_hat ([b][k][r][o], vectorized)
    uhat_kernel<<<dim3(ROUTES, BATCH / 32), 256>>>(W_obj, u, uhat);
    // 6) routing (3 iterations)
    zero_bij_kernel<<<(ROUTES * NCAPS + 255) / 256, 256>>>(bij);
    for (int it = 0; it < 3; it++) {
        softmax_routes_kernel<<<NCAPS, 256>>>(bij, cij);
        sv_kernel<<<dim3(BATCH, NCAPS), 128>>>(cij, uhat, v);
        if (it < 2)
            agree_kernel<<<dim3(NCAPS, ROUTES / 64), 256>>>(uhat, v, bij);
    }
    // 7) mask + obj output
    mask_kernel<<<2, 256>>>(v, out_obj, out_mask, best);
    // 8) decoder
    dec1_kernel<<<BATCH, 512>>>(v, best, dec_w1, dec_b1, h1);
    gemm_act_kernel<0><<<dim3(1024 / 64, BATCH / 64), 256>>>(h1, dec_w2, dec_b2, h2, BATCH, 1024, 512);
    gemm_act_kernel<1><<<dim3((784 + 63) / 64, BATCH / 64), 256>>>(h2, dec_w3, dec_b3, out_rec, BATCH, 784, 1024);
}